// round 3
// baseline (speedup 1.0000x reference)
#include <cuda_runtime.h>
#include <cuda_bf16.h>
#include <math.h>

// Problem constants
#define NB 8        // batch
#define CIN 256     // channels
#define HIMG 256
#define WIMG 256
#define HW 65536    // 256*256
#define NCH 512     // number of chunks (8 * 8 * 8)
#define CQK 32      // attn channels
#define NQ 1024     // q pixels per chunk (32*32)
#define NKV 256     // kv pixels per chunk (16*16)
#define SE 258      // energy row stride (floats) — avoids bank conflicts

// Scratch (device globals; no allocation allowed)
__device__ float g_q [(size_t)NCH * NQ * CQK];   // [b][pix][ch] 64 MB
__device__ float g_kf[(size_t)NCH * NQ * CQK];   // unpooled k    64 MB
__device__ float g_vf[(size_t)NCH * NQ * CQK];   // unpooled v    64 MB
__device__ float g_kp[(size_t)NCH * NKV * CQK];  // pooled k      16 MB
__device__ float g_vp[(size_t)NCH * NKV * CQK];  // pooled v      16 MB

// ---------------------------------------------------------------------------
// Kernel 1: fused q/k/v 1x1-conv projection.
// One CTA = one (n, h) image row = 256 pixels. 96 accumulators per thread.
// Wqkv staged in smem as [cin][96] so the inner loop is broadcast LDS.128.
// ---------------------------------------------------------------------------
__global__ __launch_bounds__(256, 2)
void qkv_kernel(const float* __restrict__ x,
                const float* __restrict__ Wq, const float* __restrict__ bq,
                const float* __restrict__ Wk, const float* __restrict__ bk,
                const float* __restrict__ Wv, const float* __restrict__ bv)
{
    extern __shared__ float sm[];
    float* Ws = sm;               // [256][96]
    float* bs = sm + 256 * 96;    // [96]

    const int t = threadIdx.x;

    for (int idx = t; idx < 256 * 96; idx += 256) {
        int cc = idx / 96;
        int o  = idx - cc * 96;
        float wv;
        if (o < 32)      wv = Wq[o * 256 + cc];
        else if (o < 64) wv = Wk[(o - 32) * 256 + cc];
        else             wv = Wv[(o - 64) * 256 + cc];
        Ws[cc * 96 + o] = wv;
    }
    if (t < 96) {
        bs[t] = (t < 32) ? bq[t] : (t < 64 ? bk[t - 32] : bv[t - 64]);
    }
    __syncthreads();

    const int bid = blockIdx.x;          // n*256 + h
    const int n = bid >> 8;
    const int h = bid & 255;
    const int w = t;

    const float* xp = x + (size_t)n * CIN * HW + (size_t)h * WIMG + w;

    float acc[96];
#pragma unroll
    for (int o = 0; o < 96; ++o) acc[o] = 0.f;

#pragma unroll 1
    for (int cc = 0; cc < 256; cc += 4) {
        float xv[4];
#pragma unroll
        for (int uu = 0; uu < 4; ++uu)
            xv[uu] = xp[(size_t)(cc + uu) * HW];
#pragma unroll
        for (int uu = 0; uu < 4; ++uu) {
            const float4* wr = (const float4*)(Ws + (cc + uu) * 96);
            float xs = xv[uu];
#pragma unroll
            for (int u = 0; u < 24; ++u) {
                float4 wv = wr[u];
                acc[4 * u + 0] = fmaf(wv.x, xs, acc[4 * u + 0]);
                acc[4 * u + 1] = fmaf(wv.y, xs, acc[4 * u + 1]);
                acc[4 * u + 2] = fmaf(wv.z, xs, acc[4 * u + 2]);
                acc[4 * u + 3] = fmaf(wv.w, xs, acc[4 * u + 3]);
            }
        }
    }

    // Epilogue: map (n,h,w) -> chunk b, pixel pix; add bias; write [b][pix][32]
    const int gx = w >> 5, j = w & 31;
    const int gy = h >> 5, i = h & 31;
    const int b = (n << 6) + (gy << 3) + gx;
    const size_t obase = ((size_t)b * NQ + (i << 5) + j) * CQK;

    float4* qo = (float4*)(g_q  + obase);
    float4* ko = (float4*)(g_kf + obase);
    float4* vo = (float4*)(g_vf + obase);
#pragma unroll
    for (int u = 0; u < 8; ++u) {
        qo[u] = make_float4(acc[4*u+0]  + bs[4*u+0],  acc[4*u+1]  + bs[4*u+1],
                            acc[4*u+2]  + bs[4*u+2],  acc[4*u+3]  + bs[4*u+3]);
        ko[u] = make_float4(acc[32+4*u+0] + bs[32+4*u+0], acc[32+4*u+1] + bs[32+4*u+1],
                            acc[32+4*u+2] + bs[32+4*u+2], acc[32+4*u+3] + bs[32+4*u+3]);
        vo[u] = make_float4(acc[64+4*u+0] + bs[64+4*u+0], acc[64+4*u+1] + bs[64+4*u+1],
                            acc[64+4*u+2] + bs[64+4*u+2], acc[64+4*u+3] + bs[64+4*u+3]);
    }
}

// ---------------------------------------------------------------------------
// Kernel 2: 2x2 max pool on k and v, [b][pix][32] -> [b][kvpix][32]
// ---------------------------------------------------------------------------
__global__ __launch_bounds__(256)
void pool_kernel()
{
    const int idx = blockIdx.x * 256 + threadIdx.x;   // 0 .. 2*512*256*8
    const int HALF = NCH * NKV * 8;
    const int which = (idx >= HALF) ? 1 : 0;
    const int r = idx - which * HALF;
    const int ch4 = r & 7;
    const int kvpix = (r >> 3) & 255;
    const int b = r >> 11;
    const int pi = kvpix >> 4, pj = kvpix & 15;

    const float* src = which ? g_vf : g_kf;
    float* dst = which ? g_vp : g_kp;

    const size_t p00 = ((size_t)b * NQ + (size_t)(2 * pi) * 32 + 2 * pj) * CQK + ch4 * 4;
    float4 a = *(const float4*)(src + p00);
    float4 c = *(const float4*)(src + p00 + 32);        // (2pi, 2pj+1)
    float4 d = *(const float4*)(src + p00 + 1024);      // (2pi+1, 2pj)
    float4 e = *(const float4*)(src + p00 + 1056);      // (2pi+1, 2pj+1)

    float4 m;
    m.x = fmaxf(fmaxf(a.x, c.x), fmaxf(d.x, e.x));
    m.y = fmaxf(fmaxf(a.y, c.y), fmaxf(d.y, e.y));
    m.z = fmaxf(fmaxf(a.z, c.z), fmaxf(d.z, e.z));
    m.w = fmaxf(fmaxf(a.w, c.w), fmaxf(d.w, e.w));

    *(float4*)(dst + ((size_t)b * NKV + kvpix) * CQK + ch4 * 4) = m;
}

// ---------------------------------------------------------------------------
// Kernel 3: per-chunk attention + output projection + residual.
// CTA = (chunk b, tile of 128 q pixels). 256 threads.
// Stage A: energy + softmax (lane pairs split kv axis, shfl reductions)
// Stage B: ao = v @ attn^T
// Stage C: out = gamma * (Wo @ ao + bo) + x
// ---------------------------------------------------------------------------
__global__ __launch_bounds__(256, 1)
void attn_kernel(const float* __restrict__ Wo, const float* __restrict__ bo,
                 const float* __restrict__ gamma,
                 const float* __restrict__ x, float* __restrict__ out)
{
    extern __shared__ float sm[];
    float* E    = sm;                    // [128][SE]
    float* Ks   = E + 128 * SE;          // [256][36]  (aliased by Wo after stage A)
    float* Vs   = Ks + 256 * 36;         // [256][32]
    float* Ao   = Vs + 256 * 32;         // [32][128]
    float* invs = Ao + 32 * 128;         // [128]

    const int t = threadIdx.x;
    const int bid = blockIdx.x;
    const int b = bid >> 3;
    const int tile = bid & 7;
    const int pixbase = tile << 7;

    // Load K (stride-36 rows: conflict-free two-row broadcast), V (packed)
    const float* kg = g_kp + (size_t)b * NKV * CQK;
    const float* vg = g_vp + (size_t)b * NKV * CQK;
    for (int idx = t; idx < NKV * CQK; idx += 256)
        Ks[(idx >> 5) * 36 + (idx & 31)] = kg[idx];
    for (int idx = t; idx < NKV * CQK / 4; idx += 256)
        ((float4*)Vs)[idx] = ((const float4*)vg)[idx];
    __syncthreads();

    // ---- Stage A: energy + softmax ----
    {
        const int pix = t >> 1, half = t & 1;
        float qr[32];
        const float4* qp4 = (const float4*)(g_q + ((size_t)b * NQ + pixbase + pix) * CQK);
#pragma unroll
        for (int u = 0; u < 8; ++u) {
            float4 v = qp4[u];
            qr[4*u+0] = v.x; qr[4*u+1] = v.y; qr[4*u+2] = v.z; qr[4*u+3] = v.w;
        }
        float* Erow = E + pix * SE;
        float m = -1e30f;
#pragma unroll 2
        for (int i = 0; i < 128; ++i) {
            const int kv = (i << 1) + half;
            const float4* kr = (const float4*)(Ks + kv * 36);
            float e = 0.f;
#pragma unroll
            for (int u = 0; u < 8; ++u) {
                float4 k4 = kr[u];
                e = fmaf(qr[4*u+0], k4.x, e);
                e = fmaf(qr[4*u+1], k4.y, e);
                e = fmaf(qr[4*u+2], k4.z, e);
                e = fmaf(qr[4*u+3], k4.w, e);
            }
            Erow[kv] = e;
            m = fmaxf(m, e);
        }
        m = fmaxf(m, __shfl_xor_sync(0xffffffffu, m, 1));
        float s = 0.f;
#pragma unroll 2
        for (int i = 0; i < 128; ++i) {
            const int kv = (i << 1) + half;
            float wv = __expf(Erow[kv] - m);
            Erow[kv] = wv;
            s += wv;
        }
        s += __shfl_xor_sync(0xffffffffu, s, 1);
        if (!half) invs[pix] = 1.f / s;
    }
    __syncthreads();

    // Load Wo into Ks space (dead after stage A). Visible after next sync.
    float* WoS = Ks;
    for (int idx = t; idx < 2048; idx += 256)
        ((float4*)WoS)[idx] = ((const float4*)Wo)[idx];

    // ---- Stage B: ao[ch][pix] = sum_kv v[ch][kv] * attn[pix][kv] ----
    {
        const int p = t & 127, cg = t >> 7;   // cg uniform per warp
        const float* er = E + p * SE;
        float acc[16];
#pragma unroll
        for (int u = 0; u < 16; ++u) acc[u] = 0.f;
#pragma unroll 2
        for (int kv = 0; kv < 256; ++kv) {
            float a = er[kv];
            const float4* vr = (const float4*)(Vs + kv * 32 + cg * 16);
            float4 v0 = vr[0], v1 = vr[1], v2 = vr[2], v3 = vr[3];
            acc[0]  = fmaf(v0.x, a, acc[0]);  acc[1]  = fmaf(v0.y, a, acc[1]);
            acc[2]  = fmaf(v0.z, a, acc[2]);  acc[3]  = fmaf(v0.w, a, acc[3]);
            acc[4]  = fmaf(v1.x, a, acc[4]);  acc[5]  = fmaf(v1.y, a, acc[5]);
            acc[6]  = fmaf(v1.z, a, acc[6]);  acc[7]  = fmaf(v1.w, a, acc[7]);
            acc[8]  = fmaf(v2.x, a, acc[8]);  acc[9]  = fmaf(v2.y, a, acc[9]);
            acc[10] = fmaf(v2.z, a, acc[10]); acc[11] = fmaf(v2.w, a, acc[11]);
            acc[12] = fmaf(v3.x, a, acc[12]); acc[13] = fmaf(v3.y, a, acc[13]);
            acc[14] = fmaf(v3.z, a, acc[14]); acc[15] = fmaf(v3.w, a, acc[15]);
        }
#pragma unroll
        for (int u = 0; u < 16; ++u)
            Ao[(cg * 16 + u) * 128 + p] = acc[u];
    }
    __syncthreads();

    // ---- Stage C: out = gamma * (Wo @ ao + bo) + x ----
    {
        const int p = t & 127, og = t >> 7;   // og uniform per warp
        const float is = invs[p];
        float ar[32];
#pragma unroll
        for (int u = 0; u < 32; ++u) ar[u] = Ao[u * 128 + p] * is;

        const int pg = pixbase + p;
        const int i = pg >> 5, j = pg & 31;
        const int n = b >> 6, gy = (b >> 3) & 7, gx = b & 7;
        const int h = (gy << 5) + i, w = (gx << 5) + j;
        const size_t base = ((size_t)n * CIN + og * 128) * HW + (size_t)h * WIMG + w;
        const float g = __ldg(gamma);

#pragma unroll 2
        for (int ol = 0; ol < 128; ++ol) {
            const int o = og * 128 + ol;
            const float4* wr = (const float4*)(WoS + o * 32);
            float v = 0.f;
#pragma unroll
            for (int u = 0; u < 8; ++u) {
                float4 w4 = wr[u];
                v = fmaf(ar[4*u+0], w4.x, v);
                v = fmaf(ar[4*u+1], w4.y, v);
                v = fmaf(ar[4*u+2], w4.z, v);
                v = fmaf(ar[4*u+3], w4.w, v);
            }
            v += __ldg(bo + o);
            const size_t off = base + (size_t)ol * HW;
            out[off] = fmaf(g, v, x[off]);
        }
    }
}

// ---------------------------------------------------------------------------
extern "C" void kernel_launch(void* const* d_in, const int* in_sizes, int n_in,
                              void* d_out, int out_size)
{
    const float* x  = (const float*)d_in[0];
    const float* Wq = (const float*)d_in[1];
    const float* bq = (const float*)d_in[2];
    const float* Wk = (const float*)d_in[3];
    const float* bk = (const float*)d_in[4];
    const float* Wv = (const float*)d_in[5];
    const float* bv = (const float*)d_in[6];
    const float* Wo = (const float*)d_in[7];
    const float* bo = (const float*)d_in[8];
    const float* gamma = (const float*)d_in[9];
    float* out = (float*)d_out;

    static bool attr_done = false;
    const int smem1 = (256 * 96 + 96) * 4;                         // 98,688 B
    const int smem3 = (128 * SE + 256 * 36 + 256 * 32 + 32 * 128 + 128) * 4; // 218,624 B
    if (!attr_done) {
        cudaFuncSetAttribute(qkv_kernel,  cudaFuncAttributeMaxDynamicSharedMemorySize, smem1);
        cudaFuncSetAttribute(attn_kernel, cudaFuncAttributeMaxDynamicSharedMemorySize, smem3);
        attr_done = true;
    }

    qkv_kernel<<<NB * HIMG, 256, smem1>>>(x, Wq, bq, Wk, bk, Wv, bv);
    pool_kernel<<<2 * NCH * NKV * 8 / 256, 256>>>();
    attn_kernel<<<NCH * 8, 256, smem3>>>(Wo, bo, gamma, x, out);
}

// round 6
// speedup vs baseline: 2.1499x; 2.1499x over previous
#include <cuda_runtime.h>
#include <cuda_bf16.h>
#include <math.h>

// Problem constants
#define NB 8
#define CIN 256
#define HW 65536
#define NCH 512
#define CQK 32
#define NQ 1024
#define NKV 256

// Scratch (device globals; no allocation allowed)
__device__ float g_q [(size_t)NCH * CQK * NQ];   // [b][ch][pix]
__device__ float g_kf[(size_t)NCH * CQK * NQ];   // [b][ch][pix]
__device__ float g_vf[(size_t)NCH * NQ * CQK];   // [b][pix][ch]
__device__ float g_kp[(size_t)NCH * CQK * NKV];  // [b][ch][kv]
__device__ float g_vp[(size_t)NCH * NKV * CQK];  // [b][kv][ch]

// ---------------------------------------------------------------------------
// Kernel 1: fused q/k/v projection. CTA = 384 threads = 12 ogroups x 32 pgroups
// covering 96 outputs x 128 pixels (half an image row). Thread tile 8 o x 4 pix.
// x staged in double-buffered smem (16 channels per block, reg-pipelined LDG).
// ---------------------------------------------------------------------------
__global__ __launch_bounds__(384, 2)
void qkv_kernel(const float* __restrict__ x,
                const float* __restrict__ Wq, const float* __restrict__ bq,
                const float* __restrict__ Wk, const float* __restrict__ bk,
                const float* __restrict__ Wv, const float* __restrict__ bv)
{
    extern __shared__ float sm[];
    float*  Ws  = sm;                       // [256][96]
    float*  bs  = sm + 24576;               // [96]
    float4* xs4 = (float4*)(sm + 24672);    // [2][16][32] float4

    const int t = threadIdx.x;

    for (int idx = t; idx < 24576; idx += 384) {
        int c = idx / 96, o = idx - c * 96;
        float wv;
        if (o < 32)      wv = Wq[o * 256 + c];
        else if (o < 64) wv = Wk[(o - 32) * 256 + c];
        else             wv = Wv[(o - 64) * 256 + c];
        Ws[c * 96 + o] = wv;
    }
    if (t < 96) bs[t] = (t < 32) ? bq[t] : (t < 64 ? bk[t - 32] : bv[t - 64]);

    const int bid = blockIdx.x;
    const int wh = bid & 1;
    const int h  = (bid >> 1) & 255;
    const int n  = bid >> 9;
    const int og = t >> 5, pg = t & 31;

    const float4* x4 = (const float4*)x;
    const size_t xbase = (size_t)n * 256 * 16384 + (size_t)h * 64 + wh * 32;

    float4 r0, r1;
    {   // prologue: load channel block 0
        int e0 = t;
        r0 = x4[xbase + (size_t)(e0 >> 5) * 16384 + (e0 & 31)];
        if (t < 128) {
            int e1 = t + 384;
            r1 = x4[xbase + (size_t)(e1 >> 5) * 16384 + (e1 & 31)];
        }
    }
    xs4[t] = r0;
    if (t < 128) xs4[t + 384] = r1;
    __syncthreads();

    float acc[32];
#pragma unroll
    for (int u = 0; u < 32; ++u) acc[u] = 0.f;

    const float4* Ws4 = (const float4*)Ws;

#pragma unroll 1
    for (int cb = 0; cb < 16; ++cb) {
        const int cur = cb & 1, nxt = cur ^ 1;
        if (cb < 15) {
            int e0 = t;
            r0 = x4[xbase + (size_t)((cb + 1) * 16 + (e0 >> 5)) * 16384 + (e0 & 31)];
            if (t < 128) {
                int e1 = t + 384;
                r1 = x4[xbase + (size_t)((cb + 1) * 16 + (e1 >> 5)) * 16384 + (e1 & 31)];
            }
        }
        const float4* xb = xs4 + cur * 512;
#pragma unroll
        for (int cc = 0; cc < 16; ++cc) {
            float4 xv = xb[cc * 32 + pg];
            float4 wa = Ws4[(cb * 16 + cc) * 24 + og * 2];
            float4 wb2 = Ws4[(cb * 16 + cc) * 24 + og * 2 + 1];
            float xr[4] = {xv.x, xv.y, xv.z, xv.w};
            float wr[8] = {wa.x, wa.y, wa.z, wa.w, wb2.x, wb2.y, wb2.z, wb2.w};
#pragma unroll
            for (int u = 0; u < 8; ++u)
#pragma unroll
                for (int r = 0; r < 4; ++r)
                    acc[u * 4 + r] = fmaf(wr[u], xr[r], acc[u * 4 + r]);
        }
        if (cb < 15) {
            xs4[nxt * 512 + t] = r0;
            if (t < 128) xs4[nxt * 512 + 384 + t] = r1;
        }
        __syncthreads();
    }

    // Epilogue
    const int gx = wh * 4 + (pg >> 3);
    const int j0 = (pg * 4) & 31;
    const int gy = h >> 5, ii = h & 31;
    const int b  = n * 64 + gy * 8 + gx;
    const int pixg = ii * 32 + j0;
    const int ob0 = og * 8;

    float bvl[8];
#pragma unroll
    for (int u = 0; u < 8; ++u) bvl[u] = bs[ob0 + u];

    if (og < 8) {
        float* dst = (og < 4) ? g_q : g_kf;
        const int c0 = ob0 & 31;
        float4* d4 = (float4*)dst + ((size_t)b * 32 + c0) * 256 + (pixg >> 2);
#pragma unroll
        for (int u = 0; u < 8; ++u)
            d4[u * 256] = make_float4(acc[u*4+0] + bvl[u], acc[u*4+1] + bvl[u],
                                      acc[u*4+2] + bvl[u], acc[u*4+3] + bvl[u]);
    } else {
        const int c0 = ob0 - 64;
#pragma unroll
        for (int r = 0; r < 4; ++r) {
            float4 v0 = make_float4(acc[0*4+r] + bvl[0], acc[1*4+r] + bvl[1],
                                    acc[2*4+r] + bvl[2], acc[3*4+r] + bvl[3]);
            float4 v1 = make_float4(acc[4*4+r] + bvl[4], acc[5*4+r] + bvl[5],
                                    acc[6*4+r] + bvl[6], acc[7*4+r] + bvl[7]);
            float4* d4 = (float4*)g_vf + ((size_t)b * 1024 + pixg + r) * 8 + (c0 >> 2);
            d4[0] = v0;
            d4[1] = v1;
        }
    }
}

// ---------------------------------------------------------------------------
// Kernel 2: 2x2 max pool.  k: [b][c][1024]->[b][c][256];  v: [b][pix][32]->[b][kv][32]
// ---------------------------------------------------------------------------
__global__ __launch_bounds__(256)
void pool_kernel()
{
    const int gid = blockIdx.x * 256 + threadIdx.x;
    if (gid < 1048576) {
        // k-plane pooling
        const int j4 = gid & 3, ip = (gid >> 2) & 15, c = (gid >> 6) & 31, b = gid >> 11;
        const float4* src = (const float4*)g_kf + ((size_t)b * 32 + c) * 256;
        const int base = (2 * ip) * 8 + j4 * 2;
        float4 a0 = src[base], a1 = src[base + 1], b0 = src[base + 8], b1 = src[base + 9];
        float4 o;
        o.x = fmaxf(fmaxf(a0.x, a0.y), fmaxf(b0.x, b0.y));
        o.y = fmaxf(fmaxf(a0.z, a0.w), fmaxf(b0.z, b0.w));
        o.z = fmaxf(fmaxf(a1.x, a1.y), fmaxf(b1.x, b1.y));
        o.w = fmaxf(fmaxf(a1.z, a1.w), fmaxf(b1.z, b1.w));
        ((float4*)g_kp)[((size_t)b * 32 + c) * 64 + ip * 4 + j4] = o;
    } else {
        const int idx = gid - 1048576;
        const int ch4 = idx & 7, kvpix = (idx >> 3) & 255, b = idx >> 11;
        const int pi = kvpix >> 4, pj = kvpix & 15;
        const float* src = g_vf + ((size_t)b * 1024 + (size_t)(2 * pi) * 32 + 2 * pj) * 32 + ch4 * 4;
        float4 a = *(const float4*)src;
        float4 c2 = *(const float4*)(src + 32);
        float4 d = *(const float4*)(src + 1024);
        float4 e = *(const float4*)(src + 1056);
        float4 m;
        m.x = fmaxf(fmaxf(a.x, c2.x), fmaxf(d.x, e.x));
        m.y = fmaxf(fmaxf(a.y, c2.y), fmaxf(d.y, e.y));
        m.z = fmaxf(fmaxf(a.z, c2.z), fmaxf(d.z, e.z));
        m.w = fmaxf(fmaxf(a.w, c2.w), fmaxf(d.w, e.w));
        *((float4*)g_vp + ((size_t)b * 256 + kvpix) * 8 + ch4) = m;
    }
}

// ---------------------------------------------------------------------------
// Kernel 3: per-chunk attention + output projection + residual.
// CTA = (chunk, 128-pixel tile), 256 threads, everything register-tiled.
// E stored [kv][pix] with additive column swizzle -> conflict-free LDS/STS.
// ---------------------------------------------------------------------------
// smem float offsets
#define OFF_E   0        // [256][32] float4 (swizzled cols), 32768 floats
#define OFF_KS  32768    // [32][256] K^T   (aliased by Wo^T [32][256] later)
#define OFF_VS  40960    // [256][32] V
#define OFF_QS  49152    // [32][128] Q^T   (aliased by Ao [32][128] later)
#define OFF_M   53248    // [128]
#define OFF_INV 53376    // [128]
#define OFF_RED 53504    // [8][132]
#define SM3_FLOATS 54560

__global__ __launch_bounds__(256, 1)
void attn_kernel(const float* __restrict__ Wo, const float* __restrict__ bo,
                 const float* __restrict__ gamma,
                 const float* __restrict__ x, float* __restrict__ out)
{
    extern __shared__ float sm[];
    float4* E4   = (float4*)sm;
    float*  KS   = sm + OFF_KS;
    float*  VS   = sm + OFF_VS;
    float*  QS   = sm + OFF_QS;
    float*  Ms   = sm + OFF_M;
    float*  INVS = sm + OFF_INV;
    float*  RED  = sm + OFF_RED;

    const int t = threadIdx.x;
    const int bid = blockIdx.x;
    const int b = bid >> 3;
    const int pixbase = (bid & 7) << 7;

    // Stage tiles: Q^T [32][128], K^T [32][256], V [256][32]
    {
        const float4* gq = (const float4*)g_q + (size_t)b * 8192 + (pixbase >> 2);
        float4* q4 = (float4*)QS;
        for (int idx = t; idx < 1024; idx += 256) {
            int c = idx >> 5, p = idx & 31;
            q4[idx] = gq[c * 256 + p];
        }
        const float4* gk = (const float4*)g_kp + (size_t)b * 2048;
        float4* k4 = (float4*)KS;
        for (int idx = t; idx < 2048; idx += 256) k4[idx] = gk[idx];
        const float4* gv = (const float4*)g_vp + (size_t)b * 2048;
        float4* v4 = (float4*)VS;
        for (int idx = t; idx < 2048; idx += 256) v4[idx] = gv[idx];
    }
    __syncthreads();

    // ---- Stage A: energy, swizzled E store, running row max ----
    {
        const int pg = t >> 3, kg = t & 7;
        const int c4s = (pg + 4 * kg) & 31;       // swizzled col4 (constant per thread)
        const float4* q4 = (const float4*)QS;
        const float4* k4 = (const float4*)KS;
        float rmax[4] = {-1e30f, -1e30f, -1e30f, -1e30f};
#pragma unroll 1
        for (int kb = 0; kb < 4; ++kb) {
            float acc[32];
#pragma unroll
            for (int u = 0; u < 32; ++u) acc[u] = 0.f;
#pragma unroll
            for (int c = 0; c < 32; ++c) {
                float4 qv = q4[c * 32 + pg];
                float4 ka = k4[c * 64 + kb * 16 + kg * 2];
                float4 kb2 = k4[c * 64 + kb * 16 + kg * 2 + 1];
                float qr[4] = {qv.x, qv.y, qv.z, qv.w};
                float kr[8] = {ka.x, ka.y, ka.z, ka.w, kb2.x, kb2.y, kb2.z, kb2.w};
#pragma unroll
                for (int u = 0; u < 8; ++u)
#pragma unroll
                    for (int r = 0; r < 4; ++r)
                        acc[u * 4 + r] = fmaf(kr[u], qr[r], acc[u * 4 + r]);
            }
#pragma unroll
            for (int u = 0; u < 8; ++u) {
                int kv = kb * 64 + kg * 8 + u;
                float4 ev = make_float4(acc[u*4+0], acc[u*4+1], acc[u*4+2], acc[u*4+3]);
                rmax[0] = fmaxf(rmax[0], ev.x);
                rmax[1] = fmaxf(rmax[1], ev.y);
                rmax[2] = fmaxf(rmax[2], ev.z);
                rmax[3] = fmaxf(rmax[3], ev.w);
                E4[kv * 32 + c4s] = ev;
            }
        }
#pragma unroll
        for (int msk = 1; msk < 8; msk <<= 1)
#pragma unroll
            for (int r = 0; r < 4; ++r)
                rmax[r] = fmaxf(rmax[r], __shfl_xor_sync(0xffffffffu, rmax[r], msk));
        if (kg == 0)
            ((float4*)Ms)[pg] = make_float4(rmax[0], rmax[1], rmax[2], rmax[3]);
    }
    __syncthreads();

    // ---- exp pass + per-pix partial sums; also stage Wo^T into dead K region ----
    {
        const int c4 = t & 31, w = t >> 5;
        float4 m4 = ((const float4*)Ms)[c4];
        float4 s4 = make_float4(0.f, 0.f, 0.f, 0.f);
#pragma unroll 8
        for (int i = 0; i < 32; ++i) {
            int kv = w + 8 * i;
            int cs = (c4 + 4 * (i & 7)) & 31;
            float4 ev = E4[kv * 32 + cs];
            ev.x = __expf(ev.x - m4.x);
            ev.y = __expf(ev.y - m4.y);
            ev.z = __expf(ev.z - m4.z);
            ev.w = __expf(ev.w - m4.w);
            E4[kv * 32 + cs] = ev;
            s4.x += ev.x; s4.y += ev.y; s4.z += ev.z; s4.w += ev.w;
        }
        RED[w * 132 + c4 * 4 + 0] = s4.x;
        RED[w * 132 + c4 * 4 + 1] = s4.y;
        RED[w * 132 + c4 * 4 + 2] = s4.z;
        RED[w * 132 + c4 * 4 + 3] = s4.w;

        // Wo^T [32c][256o] into KS (K dead after stage A)
        for (int idx = t; idx < 2048; idx += 256) {
            int o = idx >> 3, c4i = idx & 7;
            float4 wv = ((const float4*)Wo)[idx];
            KS[(c4i * 4 + 0) * 256 + o] = wv.x;
            KS[(c4i * 4 + 1) * 256 + o] = wv.y;
            KS[(c4i * 4 + 2) * 256 + o] = wv.z;
            KS[(c4i * 4 + 3) * 256 + o] = wv.w;
        }
    }
    __syncthreads();
    if (t < 128) {
        float s = 0.f;
#pragma unroll
        for (int w = 0; w < 8; ++w) s += RED[w * 132 + t];
        INVS[t] = 1.f / s;
    }
    __syncthreads();

    // ---- Stage B: Ao[ch][pix] = sum_kv V[kv][ch] * attn[kv][pix] (into QS alias) ----
    {
        const int chg = t >> 5, pg = t & 31;
        float acc[16];
#pragma unroll
        for (int u = 0; u < 16; ++u) acc[u] = 0.f;
        const float4* v4 = (const float4*)VS;
#pragma unroll 8
        for (int kv = 0; kv < 256; ++kv) {
            float4 vv = v4[kv * 8 + chg];
            int cs = (pg + 4 * ((kv >> 3) & 7)) & 31;
            float4 ev = E4[kv * 32 + cs];
            float er[4] = {ev.x, ev.y, ev.z, ev.w};
            float vr[4] = {vv.x, vv.y, vv.z, vv.w};
#pragma unroll
            for (int u = 0; u < 4; ++u)
#pragma unroll
                for (int r = 0; r < 4; ++r)
                    acc[u * 4 + r] = fmaf(vr[u], er[r], acc[u * 4 + r]);
        }
        float4 is = ((const float4*)INVS)[pg];
        float4* a4 = (float4*)QS;   // Ao alias
#pragma unroll
        for (int u = 0; u < 4; ++u)
            a4[(chg * 4 + u) * 32 + pg] =
                make_float4(acc[u*4+0] * is.x, acc[u*4+1] * is.y,
                            acc[u*4+2] * is.z, acc[u*4+3] * is.w);
    }
    __syncthreads();

    // ---- Stage C: out = gamma * (Wo @ ao + bo) + x ----
    {
        const int og = t >> 5, pg = t & 31;
        const int pix0 = pixbase + pg * 4;
        const int n = b >> 6, gy = (b >> 3) & 7, gx = b & 7;
        const int hrow = gy * 32 + (pix0 >> 5);
        const int wcol4 = gx * 8 + (pg & 7);
        const size_t obase = (size_t)n * 256 * 16384 + (size_t)hrow * 64 + wcol4;
        const float g = __ldg(gamma);
        const float4* a4 = (const float4*)QS;
        const float4* w4 = (const float4*)KS;   // Wo^T [32][64] f4
        const float4* xg4 = (const float4*)x;
        float4* o4 = (float4*)out;

#pragma unroll 1
        for (int ob = 0; ob < 8; ++ob) {
            float acc[16];
#pragma unroll
            for (int u = 0; u < 16; ++u) acc[u] = 0.f;
#pragma unroll
            for (int c = 0; c < 32; ++c) {
                float4 wv = w4[c * 64 + ob * 8 + og];
                float4 av = a4[c * 32 + pg];
                float wr[4] = {wv.x, wv.y, wv.z, wv.w};
                float ar[4] = {av.x, av.y, av.z, av.w};
#pragma unroll
                for (int u = 0; u < 4; ++u)
#pragma unroll
                    for (int r = 0; r < 4; ++r)
                        acc[u * 4 + r] = fmaf(wr[u], ar[r], acc[u * 4 + r]);
            }
            float4 bv4 = __ldg((const float4*)bo + ob * 8 + og);
            float br[4] = {bv4.x, bv4.y, bv4.z, bv4.w};
#pragma unroll
            for (int u = 0; u < 4; ++u) {
                int o = ob * 32 + og * 4 + u;
                size_t off = obase + (size_t)o * 16384;
                float4 xv = xg4[off];
                float4 rr;
                rr.x = fmaf(g, acc[u*4+0] + br[u], xv.x);
                rr.y = fmaf(g, acc[u*4+1] + br[u], xv.y);
                rr.z = fmaf(g, acc[u*4+2] + br[u], xv.z);
                rr.w = fmaf(g, acc[u*4+3] + br[u], xv.w);
                o4[off] = rr;
            }
        }
    }
}

// ---------------------------------------------------------------------------
extern "C" void kernel_launch(void* const* d_in, const int* in_sizes, int n_in,
                              void* d_out, int out_size)
{
    const float* x  = (const float*)d_in[0];
    const float* Wq = (const float*)d_in[1];
    const float* bq = (const float*)d_in[2];
    const float* Wk = (const float*)d_in[3];
    const float* bk = (const float*)d_in[4];
    const float* Wv = (const float*)d_in[5];
    const float* bv = (const float*)d_in[6];
    const float* Wo = (const float*)d_in[7];
    const float* bo = (const float*)d_in[8];
    const float* gamma = (const float*)d_in[9];
    float* out = (float*)d_out;

    const int smem1 = (24576 + 96 + 4096) * 4;      // 115,072 B
    const int smem3 = SM3_FLOATS * 4;               // 218,240 B
    cudaFuncSetAttribute(qkv_kernel,  cudaFuncAttributeMaxDynamicSharedMemorySize, smem1);
    cudaFuncSetAttribute(attn_kernel, cudaFuncAttributeMaxDynamicSharedMemorySize, smem3);

    qkv_kernel<<<4096, 384, smem1>>>(x, Wq, bq, Wk, bk, Wv, bv);
    pool_kernel<<<8192, 256>>>();
    attn_kernel<<<4096, 256, smem3>>>(Wo, bo, gamma, x, out);
}

// round 8
// speedup vs baseline: 2.7874x; 1.2965x over previous
#include <cuda_runtime.h>
#include <cuda_bf16.h>
#include <math.h>
#include <cstdint>

// Problem constants
#define NB 8
#define CIN 256
#define HW 65536
#define NCH 512
#define CQK 32
#define NQ 1024
#define NKV 256

// Scratch (device globals; no allocation allowed)
__device__ float g_q [(size_t)NCH * CQK * NQ];   // [b][ch][pix]
__device__ float g_kf[(size_t)NCH * CQK * NQ];   // [b][ch][pix]
__device__ float g_vf[(size_t)NCH * CQK * NQ];   // [b][ch][pix]
__device__ float g_kp[(size_t)NCH * CQK * NKV];  // [b][ch][kv]
__device__ float g_vp[(size_t)NCH * CQK * NKV];  // [b][ch][kv]

// ===========================================================================
// helpers
// ===========================================================================
__device__ __forceinline__ uint32_t s2u32(const void* p) {
    uint32_t a;
    asm("{ .reg .u64 t; cvta.to.shared.u64 t, %1; cvt.u32.u64 %0, t; }" : "=r"(a) : "l"(p));
    return a;
}
__device__ __forceinline__ uint32_t f2bf2(float lo, float hi) {
    uint32_t r;
    asm("cvt.rn.bf16x2.f32 %0, %1, %2;" : "=r"(r) : "f"(hi), "f"(lo));
    return r;
}
__device__ __forceinline__ float bf_lo(uint32_t h) { return __uint_as_float(h << 16); }
__device__ __forceinline__ float bf_hi(uint32_t h) { return __uint_as_float(h & 0xffff0000u); }

__device__ __forceinline__ void mma16816(float* c, const uint32_t* a, uint32_t b0, uint32_t b1) {
    asm volatile(
        "mma.sync.aligned.m16n8k16.row.col.f32.bf16.bf16.f32 "
        "{%0,%1,%2,%3}, {%4,%5,%6,%7}, {%8,%9}, {%0,%1,%2,%3};"
        : "+f"(c[0]), "+f"(c[1]), "+f"(c[2]), "+f"(c[3])
        : "r"(a[0]), "r"(a[1]), "r"(a[2]), "r"(a[3]), "r"(b0), "r"(b1));
}

#define CP_ASYNC16(dst, src) \
    asm volatile("cp.async.ca.shared.global [%0], [%1], 16;" :: "r"(dst), "l"(src) : "memory")
#define CP_COMMIT() asm volatile("cp.async.commit_group;" ::: "memory")
#define CP_WAIT0()  asm volatile("cp.async.wait_group 0;" ::: "memory")

// qkv smem layout (bytes)
#define OFF_W2HI  0           // [96][132] u32  (k-pairs, +4 pad)
#define OFF_W2LO  50688
#define OFF_BIAS  101376      // [96] float
#define OFF_XS    101760      // 2 x [32][268] float  (raw fp32 x chunks)
#define XS_FLOATS 8576        // 32*268
#define QKV_SMEM  170368

// ---------------------------------------------------------------------------
// Kernel 1: q/k/v projection via mma.sync bf16 hi/lo 3-pass.
// CTA = one (n,h) image row: 96 outputs x 256 pixels, K=256.
// 8 warps: warpM (2) x warpN (4); warp tile 48 x 64.
// ---------------------------------------------------------------------------
__global__ __launch_bounds__(256, 1)
void qkv_mma_kernel(const float* __restrict__ x,
                    const float* __restrict__ Wq, const float* __restrict__ bq,
                    const float* __restrict__ Wk, const float* __restrict__ bk,
                    const float* __restrict__ Wv, const float* __restrict__ bv)
{
    extern __shared__ __align__(16) char smem[];
    const uint32_t sbase = s2u32(smem);
    uint32_t* W2hi = (uint32_t*)(smem + OFF_W2HI);
    uint32_t* W2lo = (uint32_t*)(smem + OFF_W2LO);
    float*    bias = (float*)(smem + OFF_BIAS);
    float*    xsm  = (float*)(smem + OFF_XS);

    const int t = threadIdx.x;
    const int wid = t >> 5, lane = t & 31;
    const int g = lane >> 2, tig = lane & 3;
    const int warpM = wid >> 2, warpN = wid & 3;
    const int m0 = warpM * 48;
    const int n0w = warpN * 64;

    const int bid = blockIdx.x;
    const int h = bid & 255;
    const int n = bid >> 8;

    const float* xrow = x + (size_t)n * (256 * 65536) + (size_t)h * 256;

    // ---- issue chunk 0 cp.async first (overlap with W conversion) ----
    {
        const uint32_t dstb = sbase + OFF_XS;
#pragma unroll
        for (int i = 0; i < 8; ++i) {
            int item = t + i * 256;
            int ch = item >> 6, p4 = item & 63;
            CP_ASYNC16(dstb + (uint32_t)(ch * 268 + p4 * 4) * 4,
                       xrow + (size_t)ch * 65536 + p4 * 4);
        }
        CP_COMMIT();
    }

    // ---- convert W (96x256) -> bf16 hi/lo k-pair smem ----
    for (int item = t; item < 96 * 128; item += 256) {
        int m = item >> 7, kk = item & 127;
        const float* wrow = (m < 32) ? (Wq + m * 256)
                          : (m < 64) ? (Wk + (m - 32) * 256)
                                     : (Wv + (m - 64) * 256);
        float f0 = wrow[2 * kk], f1 = wrow[2 * kk + 1];
        uint32_t hi = f2bf2(f0, f1);
        uint32_t lo = f2bf2(f0 - bf_lo(hi), f1 - bf_hi(hi));
        W2hi[m * 132 + kk] = hi;
        W2lo[m * 132 + kk] = lo;
    }
    if (t < 96) bias[t] = (t < 32) ? bq[t] : (t < 64 ? bk[t - 32] : bv[t - 64]);

    float acc[3][8][4];
#pragma unroll
    for (int mt = 0; mt < 3; ++mt)
#pragma unroll
        for (int nt = 0; nt < 8; ++nt)
#pragma unroll
            for (int u = 0; u < 4; ++u) acc[mt][nt][u] = 0.f;

    CP_WAIT0();
    __syncthreads();

    // ---- main K loop: 8 chunks of 32 channels ----
#pragma unroll 1
    for (int cc = 0; cc < 8; ++cc) {
        if (cc < 7) {   // stream next chunk while computing this one
            const uint32_t dstb = sbase + OFF_XS + (uint32_t)(((cc + 1) & 1) * XS_FLOATS * 4);
            const float* srcb = xrow + (size_t)(cc + 1) * 32 * 65536;
#pragma unroll
            for (int i = 0; i < 8; ++i) {
                int item = t + i * 256;
                int ch = item >> 6, p4 = item & 63;
                CP_ASYNC16(dstb + (uint32_t)(ch * 268 + p4 * 4) * 4,
                           srcb + (size_t)ch * 65536 + p4 * 4);
            }
            CP_COMMIT();
        }

        const float* xsf = xsm + (cc & 1) * XS_FLOATS;
        const int kkc = cc * 16;

#pragma unroll
        for (int s = 0; s < 2; ++s) {
            const int ks = s * 16;
            const int kk0 = kkc + s * 8 + tig;

            // A fragments (bf16 hi/lo from smem W2)
            uint32_t Ahi[3][4], Alo[3][4];
#pragma unroll
            for (int mt = 0; mt < 3; ++mt) {
                const int r0 = (m0 + mt * 16 + g) * 132;
                const int r8 = r0 + 8 * 132;
                Ahi[mt][0] = W2hi[r0 + kk0];
                Ahi[mt][1] = W2hi[r8 + kk0];
                Ahi[mt][2] = W2hi[r0 + kk0 + 4];
                Ahi[mt][3] = W2hi[r8 + kk0 + 4];
                Alo[mt][0] = W2lo[r0 + kk0];
                Alo[mt][1] = W2lo[r8 + kk0];
                Alo[mt][2] = W2lo[r0 + kk0 + 4];
                Alo[mt][3] = W2lo[r8 + kk0 + 4];
            }

#pragma unroll
            for (int nt = 0; nt < 8; ++nt) {
                const int base = (ks + 2 * tig) * 268 + n0w + nt * 8 + g;
                float x0 = xsf[base];
                float x1 = xsf[base + 268];
                float x2 = xsf[base + 8 * 268];
                float x3 = xsf[base + 9 * 268];
                uint32_t bhi0 = f2bf2(x0, x1);
                uint32_t bhi1 = f2bf2(x2, x3);
                uint32_t blo0 = f2bf2(x0 - bf_lo(bhi0), x1 - bf_hi(bhi0));
                uint32_t blo1 = f2bf2(x2 - bf_lo(bhi1), x3 - bf_hi(bhi1));
#pragma unroll
                for (int mt = 0; mt < 3; ++mt) {
                    mma16816(acc[mt][nt], Ahi[mt], bhi0, bhi1);
                    mma16816(acc[mt][nt], Ahi[mt], blo0, blo1);
                    mma16816(acc[mt][nt], Alo[mt], bhi0, bhi1);
                }
            }
        }

        if (cc < 7) CP_WAIT0();
        __syncthreads();
    }

    // ---- epilogue: bias + scatter to planar [b][ch][pix] ----
    {
        const int gy = h >> 5, ii = h & 31;
#pragma unroll
        for (int mt = 0; mt < 3; ++mt) {
            const int mbase = m0 + mt * 16;
            const int aidx = mbase >> 5;
            float* arr = (aidx == 0) ? g_q : (aidx == 1) ? g_kf : g_vf;
            const int ch = (mbase & 31) + g;
            const float b1 = bias[mbase + g];
            const float b2 = bias[mbase + 8 + g];
#pragma unroll
            for (int nt = 0; nt < 8; ++nt) {
                const int w = n0w + nt * 8 + tig * 2;
                const int gx = w >> 5;
                const int b = n * 64 + gy * 8 + gx;
                const int pix = ii * 32 + (w & 31);
                float2* d0 = (float2*)(arr + ((size_t)(b * 32 + ch)) * 1024 + pix);
                float2* d1 = (float2*)(arr + ((size_t)(b * 32 + ch + 8)) * 1024 + pix);
                *d0 = make_float2(acc[mt][nt][0] + b1, acc[mt][nt][1] + b1);
                *d1 = make_float2(acc[mt][nt][2] + b2, acc[mt][nt][3] + b2);
            }
        }
    }
}

// ---------------------------------------------------------------------------
// Kernel 2: 2x2 max pool, planar [b][ch][1024] -> [b][ch][256] for k and v
// ---------------------------------------------------------------------------
__global__ __launch_bounds__(256)
void pool_kernel()
{
    const int gid = blockIdx.x * 256 + threadIdx.x;
    const int which = (gid >= 1048576) ? 1 : 0;
    const int r = gid & 1048575;
    const int j4 = r & 3, ip = (r >> 2) & 15, c = (r >> 6) & 31, b = r >> 11;
    const float4* src = (const float4*)(which ? g_vf : g_kf) + ((size_t)b * 32 + c) * 256;
    float4* dst = (float4*)(which ? g_vp : g_kp);
    const int base = (2 * ip) * 8 + j4 * 2;
    float4 a0 = src[base], a1 = src[base + 1], b0 = src[base + 8], b1 = src[base + 9];
    float4 o;
    o.x = fmaxf(fmaxf(a0.x, a0.y), fmaxf(b0.x, b0.y));
    o.y = fmaxf(fmaxf(a0.z, a0.w), fmaxf(b0.z, b0.w));
    o.z = fmaxf(fmaxf(a1.x, a1.y), fmaxf(b1.x, b1.y));
    o.w = fmaxf(fmaxf(a1.z, a1.w), fmaxf(b1.z, b1.w));
    dst[((size_t)b * 32 + c) * 64 + ip * 4 + j4] = o;
}

// ---------------------------------------------------------------------------
// Kernel 3: per-chunk attention + output projection + residual.
// ---------------------------------------------------------------------------
#define OFF_E   0        // [256 kv][32 pix-f4] swizzled, 32768 floats
#define OFF_KS  32768    // [32][256] K^T (aliased by Wo^T later)
#define OFF_VS  40960    // [32][256] V (channel-major)
#define OFF_QS  49152    // [32][128] Q^T (aliased by Ao later)
#define OFF_M   53248
#define OFF_INV 53376
#define OFF_RED 53504
#define SM3_FLOATS 54560

__global__ __launch_bounds__(256, 1)
void attn_kernel(const float* __restrict__ Wo, const float* __restrict__ bo,
                 const float* __restrict__ gamma,
                 const float* __restrict__ x, float* __restrict__ out)
{
    extern __shared__ float sm[];
    float4* E4   = (float4*)sm;
    float*  KS   = sm + OFF_KS;
    float*  VS   = sm + OFF_VS;
    float*  QS   = sm + OFF_QS;
    float*  Ms   = sm + OFF_M;
    float*  INVS = sm + OFF_INV;
    float*  RED  = sm + OFF_RED;

    const int t = threadIdx.x;
    const int bid = blockIdx.x;
    const int b = bid >> 3;
    const int pixbase = (bid & 7) << 7;

    // Stage tiles: Q^T [32][128], K^T [32][256], V [32][256]
    {
        const float4* gq = (const float4*)g_q + (size_t)b * 8192 + (pixbase >> 2);
        float4* q4 = (float4*)QS;
        for (int idx = t; idx < 1024; idx += 256) {
            int c = idx >> 5, p = idx & 31;
            q4[idx] = gq[c * 256 + p];
        }
        const float4* gk = (const float4*)g_kp + (size_t)b * 2048;
        float4* k4 = (float4*)KS;
        for (int idx = t; idx < 2048; idx += 256) k4[idx] = gk[idx];
        const float4* gv = (const float4*)g_vp + (size_t)b * 2048;
        float4* v4 = (float4*)VS;
        for (int idx = t; idx < 2048; idx += 256) v4[idx] = gv[idx];
    }
    __syncthreads();

    // ---- Stage A: energy, swizzled E store, running row max ----
    {
        const int pg = t >> 3, kg = t & 7;
        const int c4s = (pg + 4 * kg) & 31;
        const float4* q4 = (const float4*)QS;
        const float4* k4 = (const float4*)KS;
        float rmax[4] = {-1e30f, -1e30f, -1e30f, -1e30f};
#pragma unroll 1
        for (int kb = 0; kb < 4; ++kb) {
            float acc[32];
#pragma unroll
            for (int u = 0; u < 32; ++u) acc[u] = 0.f;
#pragma unroll
            for (int c = 0; c < 32; ++c) {
                float4 qv = q4[c * 32 + pg];
                float4 ka = k4[c * 64 + kb * 16 + kg * 2];
                float4 kb2 = k4[c * 64 + kb * 16 + kg * 2 + 1];
                float qr[4] = {qv.x, qv.y, qv.z, qv.w};
                float kr[8] = {ka.x, ka.y, ka.z, ka.w, kb2.x, kb2.y, kb2.z, kb2.w};
#pragma unroll
                for (int u = 0; u < 8; ++u)
#pragma unroll
                    for (int r = 0; r < 4; ++r)
                        acc[u * 4 + r] = fmaf(kr[u], qr[r], acc[u * 4 + r]);
            }
#pragma unroll
            for (int u = 0; u < 8; ++u) {
                int kv = kb * 64 + kg * 8 + u;
                float4 ev = make_float4(acc[u*4+0], acc[u*4+1], acc[u*4+2], acc[u*4+3]);
                rmax[0] = fmaxf(rmax[0], ev.x);
                rmax[1] = fmaxf(rmax[1], ev.y);
                rmax[2] = fmaxf(rmax[2], ev.z);
                rmax[3] = fmaxf(rmax[3], ev.w);
                E4[kv * 32 + c4s] = ev;
            }
        }
#pragma unroll
        for (int msk = 1; msk < 8; msk <<= 1)
#pragma unroll
            for (int r = 0; r < 4; ++r)
                rmax[r] = fmaxf(rmax[r], __shfl_xor_sync(0xffffffffu, rmax[r], msk));
        if (kg == 0)
            ((float4*)Ms)[pg] = make_float4(rmax[0], rmax[1], rmax[2], rmax[3]);
    }
    __syncthreads();

    // ---- exp pass + per-pix partial sums; stage Wo^T into dead K region ----
    {
        const int c4 = t & 31, w = t >> 5;
        float4 m4 = ((const float4*)Ms)[c4];
        float4 s4 = make_float4(0.f, 0.f, 0.f, 0.f);
#pragma unroll 8
        for (int i = 0; i < 32; ++i) {
            int kv = w + 8 * i;
            int cs = (c4 + 4 * (i & 7)) & 31;
            float4 ev = E4[kv * 32 + cs];
            ev.x = __expf(ev.x - m4.x);
            ev.y = __expf(ev.y - m4.y);
            ev.z = __expf(ev.z - m4.z);
            ev.w = __expf(ev.w - m4.w);
            E4[kv * 32 + cs] = ev;
            s4.x += ev.x; s4.y += ev.y; s4.z += ev.z; s4.w += ev.w;
        }
        RED[w * 132 + c4 * 4 + 0] = s4.x;
        RED[w * 132 + c4 * 4 + 1] = s4.y;
        RED[w * 132 + c4 * 4 + 2] = s4.z;
        RED[w * 132 + c4 * 4 + 3] = s4.w;

        for (int idx = t; idx < 2048; idx += 256) {
            int o = idx >> 3, c4i = idx & 7;
            float4 wv = ((const float4*)Wo)[idx];
            KS[(c4i * 4 + 0) * 256 + o] = wv.x;
            KS[(c4i * 4 + 1) * 256 + o] = wv.y;
            KS[(c4i * 4 + 2) * 256 + o] = wv.z;
            KS[(c4i * 4 + 3) * 256 + o] = wv.w;
        }
    }
    __syncthreads();
    if (t < 128) {
        float s = 0.f;
#pragma unroll
        for (int w = 0; w < 8; ++w) s += RED[w * 132 + t];
        INVS[t] = 1.f / s;
    }
    __syncthreads();

    // ---- Stage B: Ao[ch][pix] = sum_kv V[ch][kv] * attn[kv][pix] ----
    {
        const int chg = t >> 5, pg = t & 31;
        float acc[16];
#pragma unroll
        for (int u = 0; u < 16; ++u) acc[u] = 0.f;
        const float4* v4 = (const float4*)VS;
#pragma unroll 2
        for (int kv4 = 0; kv4 < 64; ++kv4) {
            float vcf[16];
#pragma unroll
            for (int u = 0; u < 4; ++u) {
                float4 vv = v4[(chg * 4 + u) * 64 + kv4];
                vcf[u * 4 + 0] = vv.x; vcf[u * 4 + 1] = vv.y;
                vcf[u * 4 + 2] = vv.z; vcf[u * 4 + 3] = vv.w;
            }
#pragma unroll
            for (int r2 = 0; r2 < 4; ++r2) {
                int kv = kv4 * 4 + r2;
                int cs = (pg + 4 * ((kv >> 3) & 7)) & 31;
                float4 ev = E4[kv * 32 + cs];
#pragma unroll
                for (int u = 0; u < 4; ++u) {
                    float vu = vcf[u * 4 + r2];
                    acc[u * 4 + 0] = fmaf(vu, ev.x, acc[u * 4 + 0]);
                    acc[u * 4 + 1] = fmaf(vu, ev.y, acc[u * 4 + 1]);
                    acc[u * 4 + 2] = fmaf(vu, ev.z, acc[u * 4 + 2]);
                    acc[u * 4 + 3] = fmaf(vu, ev.w, acc[u * 4 + 3]);
                }
            }
        }
        float4 is = ((const float4*)INVS)[pg];
        float4* a4 = (float4*)QS;
#pragma unroll
        for (int u = 0; u < 4; ++u)
            a4[(chg * 4 + u) * 32 + pg] =
                make_float4(acc[u*4+0] * is.x, acc[u*4+1] * is.y,
                            acc[u*4+2] * is.z, acc[u*4+3] * is.w);
    }
    __syncthreads();

    // ---- Stage C: out = gamma * (Wo @ ao + bo) + x ----
    {
        const int og = t >> 5, pg = t & 31;
        const int pix0 = pixbase + pg * 4;
        const int n = b >> 6, gy = (b >> 3) & 7, gx = b & 7;
        const int hrow = gy * 32 + (pix0 >> 5);
        const int wcol4 = gx * 8 + (pg & 7);
        const size_t obase = (size_t)n * 256 * 16384 + (size_t)hrow * 64 + wcol4;
        const float g = __ldg(gamma);
        const float4* a4 = (const float4*)QS;
        const float4* w4 = (const float4*)KS;
        const float4* xg4 = (const float4*)x;
        float4* o4 = (float4*)out;

#pragma unroll 1
        for (int ob = 0; ob < 8; ++ob) {
            float acc[16];
#pragma unroll
            for (int u = 0; u < 16; ++u) acc[u] = 0.f;
#pragma unroll
            for (int c = 0; c < 32; ++c) {
                float4 wv = w4[c * 64 + ob * 8 + og];
                float4 av = a4[c * 32 + pg];
                float wr[4] = {wv.x, wv.y, wv.z, wv.w};
                float ar[4] = {av.x, av.y, av.z, av.w};
#pragma unroll
                for (int u = 0; u < 4; ++u)
#pragma unroll
                    for (int r = 0; r < 4; ++r)
                        acc[u * 4 + r] = fmaf(wr[u], ar[r], acc[u * 4 + r]);
            }
            float4 bv4 = __ldg((const float4*)bo + ob * 8 + og);
            float br[4] = {bv4.x, bv4.y, bv4.z, bv4.w};
#pragma unroll
            for (int u = 0; u < 4; ++u) {
                int o = ob * 32 + og * 4 + u;
                size_t off = obase + (size_t)o * 16384;
                float4 xv = xg4[off];
                float4 rr;
                rr.x = fmaf(g, acc[u*4+0] + br[u], xv.x);
                rr.y = fmaf(g, acc[u*4+1] + br[u], xv.y);
                rr.z = fmaf(g, acc[u*4+2] + br[u], xv.z);
                rr.w = fmaf(g, acc[u*4+3] + br[u], xv.w);
                o4[off] = rr;
            }
        }
    }
}

// ---------------------------------------------------------------------------
extern "C" void kernel_launch(void* const* d_in, const int* in_sizes, int n_in,
                              void* d_out, int out_size)
{
    const float* x  = (const float*)d_in[0];
    const float* Wq = (const float*)d_in[1];
    const float* bq = (const float*)d_in[2];
    const float* Wk = (const float*)d_in[3];
    const float* bk = (const float*)d_in[4];
    const float* Wv = (const float*)d_in[5];
    const float* bv = (const float*)d_in[6];
    const float* Wo = (const float*)d_in[7];
    const float* bo = (const float*)d_in[8];
    const float* gamma = (const float*)d_in[9];
    float* out = (float*)d_out;

    const int smem3 = SM3_FLOATS * 4;   // 218,240 B
    cudaFuncSetAttribute(qkv_mma_kernel, cudaFuncAttributeMaxDynamicSharedMemorySize, QKV_SMEM);
    cudaFuncSetAttribute(attn_kernel, cudaFuncAttributeMaxDynamicSharedMemorySize, smem3);

    qkv_mma_kernel<<<2048, 256, QKV_SMEM>>>(x, Wq, bq, Wk, bk, Wv, bv);
    pool_kernel<<<8192, 256>>>();
    attn_kernel<<<4096, 256, smem3>>>(Wo, bo, gamma, x, out);
}

// round 9
// speedup vs baseline: 3.0938x; 1.1099x over previous
#include <cuda_runtime.h>
#include <cuda_bf16.h>
#include <math.h>
#include <cstdint>

// Problem constants
#define NB 8
#define CIN 256
#define HW 65536
#define NCH 512
#define CQK 32
#define NQ 1024
#define NKV 256

// Scratch (device globals; no allocation allowed)
__device__ float g_q [(size_t)NCH * CQK * NQ];   // [b][ch][pix]
__device__ float g_kf[(size_t)NCH * CQK * NQ];   // [b][ch][pix]
__device__ float g_vf[(size_t)NCH * CQK * NQ];   // [b][ch][pix]
__device__ float g_kp[(size_t)NCH * CQK * NKV];  // [b][ch][kv]
__device__ float g_vp[(size_t)NCH * CQK * NKV];  // [b][ch][kv]

// ===========================================================================
// helpers
// ===========================================================================
__device__ __forceinline__ uint32_t s2u32(const void* p) {
    uint32_t a;
    asm("{ .reg .u64 t; cvta.to.shared.u64 t, %1; cvt.u32.u64 %0, t; }" : "=r"(a) : "l"(p));
    return a;
}
__device__ __forceinline__ uint32_t f2bf2(float lo, float hi) {
    uint32_t r;
    asm("cvt.rn.bf16x2.f32 %0, %1, %2;" : "=r"(r) : "f"(hi), "f"(lo));
    return r;
}
__device__ __forceinline__ float bf_lo(uint32_t h) { return __uint_as_float(h << 16); }
__device__ __forceinline__ float bf_hi(uint32_t h) { return __uint_as_float(h & 0xffff0000u); }

__device__ __forceinline__ void mma16816(float* c, const uint32_t* a, uint32_t b0, uint32_t b1) {
    asm volatile(
        "mma.sync.aligned.m16n8k16.row.col.f32.bf16.bf16.f32 "
        "{%0,%1,%2,%3}, {%4,%5,%6,%7}, {%8,%9}, {%0,%1,%2,%3};"
        : "+f"(c[0]), "+f"(c[1]), "+f"(c[2]), "+f"(c[3])
        : "r"(a[0]), "r"(a[1]), "r"(a[2]), "r"(a[3]), "r"(b0), "r"(b1));
}

#define CP_ASYNC16(dst, src) \
    asm volatile("cp.async.ca.shared.global [%0], [%1], 16;" :: "r"(dst), "l"(src) : "memory")
#define CP_COMMIT() asm volatile("cp.async.commit_group;" ::: "memory")
#define CP_WAIT0()  asm volatile("cp.async.wait_group 0;" ::: "memory")

// ===========================================================================
// Kernel 1: q/k/v projection via mma.sync bf16 hi/lo 3-pass. (round-8, passing)
// ===========================================================================
#define OFF_W2HI  0
#define OFF_W2LO  50688
#define OFF_BIAS  101376
#define OFF_XS    101760
#define XS_FLOATS 8576
#define QKV_SMEM  170368

__global__ __launch_bounds__(256, 1)
void qkv_mma_kernel(const float* __restrict__ x,
                    const float* __restrict__ Wq, const float* __restrict__ bq,
                    const float* __restrict__ Wk, const float* __restrict__ bk,
                    const float* __restrict__ Wv, const float* __restrict__ bv)
{
    extern __shared__ __align__(16) char smem[];
    const uint32_t sbase = s2u32(smem);
    uint32_t* W2hi = (uint32_t*)(smem + OFF_W2HI);
    uint32_t* W2lo = (uint32_t*)(smem + OFF_W2LO);
    float*    bias = (float*)(smem + OFF_BIAS);
    float*    xsm  = (float*)(smem + OFF_XS);

    const int t = threadIdx.x;
    const int wid = t >> 5, lane = t & 31;
    const int g = lane >> 2, tig = lane & 3;
    const int warpM = wid >> 2, warpN = wid & 3;
    const int m0 = warpM * 48;
    const int n0w = warpN * 64;

    const int bid = blockIdx.x;
    const int h = bid & 255;
    const int n = bid >> 8;

    const float* xrow = x + (size_t)n * (256 * 65536) + (size_t)h * 256;

    {
        const uint32_t dstb = sbase + OFF_XS;
#pragma unroll
        for (int i = 0; i < 8; ++i) {
            int item = t + i * 256;
            int ch = item >> 6, p4 = item & 63;
            CP_ASYNC16(dstb + (uint32_t)(ch * 268 + p4 * 4) * 4,
                       xrow + (size_t)ch * 65536 + p4 * 4);
        }
        CP_COMMIT();
    }

    for (int item = t; item < 96 * 128; item += 256) {
        int m = item >> 7, kk = item & 127;
        const float* wrow = (m < 32) ? (Wq + m * 256)
                          : (m < 64) ? (Wk + (m - 32) * 256)
                                     : (Wv + (m - 64) * 256);
        float f0 = wrow[2 * kk], f1 = wrow[2 * kk + 1];
        uint32_t hi = f2bf2(f0, f1);
        uint32_t lo = f2bf2(f0 - bf_lo(hi), f1 - bf_hi(hi));
        W2hi[m * 132 + kk] = hi;
        W2lo[m * 132 + kk] = lo;
    }
    if (t < 96) bias[t] = (t < 32) ? bq[t] : (t < 64 ? bk[t - 32] : bv[t - 64]);

    float acc[3][8][4];
#pragma unroll
    for (int mt = 0; mt < 3; ++mt)
#pragma unroll
        for (int nt = 0; nt < 8; ++nt)
#pragma unroll
            for (int u = 0; u < 4; ++u) acc[mt][nt][u] = 0.f;

    CP_WAIT0();
    __syncthreads();

#pragma unroll 1
    for (int cc = 0; cc < 8; ++cc) {
        if (cc < 7) {
            const uint32_t dstb = sbase + OFF_XS + (uint32_t)(((cc + 1) & 1) * XS_FLOATS * 4);
            const float* srcb = xrow + (size_t)(cc + 1) * 32 * 65536;
#pragma unroll
            for (int i = 0; i < 8; ++i) {
                int item = t + i * 256;
                int ch = item >> 6, p4 = item & 63;
                CP_ASYNC16(dstb + (uint32_t)(ch * 268 + p4 * 4) * 4,
                           srcb + (size_t)ch * 65536 + p4 * 4);
            }
            CP_COMMIT();
        }

        const float* xsf = xsm + (cc & 1) * XS_FLOATS;
        const int kkc = cc * 16;

#pragma unroll
        for (int s = 0; s < 2; ++s) {
            const int ks = s * 16;
            const int kk0 = kkc + s * 8 + tig;

            uint32_t Ahi[3][4], Alo[3][4];
#pragma unroll
            for (int mt = 0; mt < 3; ++mt) {
                const int r0 = (m0 + mt * 16 + g) * 132;
                const int r8 = r0 + 8 * 132;
                Ahi[mt][0] = W2hi[r0 + kk0];
                Ahi[mt][1] = W2hi[r8 + kk0];
                Ahi[mt][2] = W2hi[r0 + kk0 + 4];
                Ahi[mt][3] = W2hi[r8 + kk0 + 4];
                Alo[mt][0] = W2lo[r0 + kk0];
                Alo[mt][1] = W2lo[r8 + kk0];
                Alo[mt][2] = W2lo[r0 + kk0 + 4];
                Alo[mt][3] = W2lo[r8 + kk0 + 4];
            }

#pragma unroll
            for (int nt = 0; nt < 8; ++nt) {
                const int base = (ks + 2 * tig) * 268 + n0w + nt * 8 + g;
                float x0 = xsf[base];
                float x1 = xsf[base + 268];
                float x2 = xsf[base + 8 * 268];
                float x3 = xsf[base + 9 * 268];
                uint32_t bhi0 = f2bf2(x0, x1);
                uint32_t bhi1 = f2bf2(x2, x3);
                uint32_t blo0 = f2bf2(x0 - bf_lo(bhi0), x1 - bf_hi(bhi0));
                uint32_t blo1 = f2bf2(x2 - bf_lo(bhi1), x3 - bf_hi(bhi1));
#pragma unroll
                for (int mt = 0; mt < 3; ++mt) {
                    mma16816(acc[mt][nt], Ahi[mt], bhi0, bhi1);
                    mma16816(acc[mt][nt], Ahi[mt], blo0, blo1);
                    mma16816(acc[mt][nt], Alo[mt], bhi0, bhi1);
                }
            }
        }

        if (cc < 7) CP_WAIT0();
        __syncthreads();
    }

    {
        const int gy = h >> 5, ii = h & 31;
#pragma unroll
        for (int mt = 0; mt < 3; ++mt) {
            const int mbase = m0 + mt * 16;
            const int aidx = mbase >> 5;
            float* arr = (aidx == 0) ? g_q : (aidx == 1) ? g_kf : g_vf;
            const int ch = (mbase & 31) + g;
            const float b1 = bias[mbase + g];
            const float b2 = bias[mbase + 8 + g];
#pragma unroll
            for (int nt = 0; nt < 8; ++nt) {
                const int w = n0w + nt * 8 + tig * 2;
                const int gx = w >> 5;
                const int b = n * 64 + gy * 8 + gx;
                const int pix = ii * 32 + (w & 31);
                float2* d0 = (float2*)(arr + ((size_t)(b * 32 + ch)) * 1024 + pix);
                float2* d1 = (float2*)(arr + ((size_t)(b * 32 + ch + 8)) * 1024 + pix);
                *d0 = make_float2(acc[mt][nt][0] + b1, acc[mt][nt][1] + b1);
                *d1 = make_float2(acc[mt][nt][2] + b2, acc[mt][nt][3] + b2);
            }
        }
    }
}

// ===========================================================================
// Kernel 2: 2x2 max pool, planar [b][ch][1024] -> [b][ch][256]
// ===========================================================================
__global__ __launch_bounds__(256)
void pool_kernel()
{
    const int gid = blockIdx.x * 256 + threadIdx.x;
    const int which = (gid >= 1048576) ? 1 : 0;
    const int r = gid & 1048575;
    const int j4 = r & 3, ip = (r >> 2) & 15, c = (r >> 6) & 31, b = r >> 11;
    const float4* src = (const float4*)(which ? g_vf : g_kf) + ((size_t)b * 32 + c) * 256;
    float4* dst = (float4*)(which ? g_vp : g_kp);
    const int base = (2 * ip) * 8 + j4 * 2;
    float4 a0 = src[base], a1 = src[base + 1], b0 = src[base + 8], b1 = src[base + 9];
    float4 o;
    o.x = fmaxf(fmaxf(a0.x, a0.y), fmaxf(b0.x, b0.y));
    o.y = fmaxf(fmaxf(a0.z, a0.w), fmaxf(b0.z, b0.w));
    o.z = fmaxf(fmaxf(a1.x, a1.y), fmaxf(b1.x, b1.y));
    o.w = fmaxf(fmaxf(a1.z, a1.w), fmaxf(b1.z, b1.w));
    dst[((size_t)b * 32 + c) * 64 + ip * 4 + j4] = o;
}

// ===========================================================================
// Kernel 3: attention fully on mma.sync.
// CTA = (chunk, 128-pix tile), 256 threads = 8 warps (warpM 2 x warpN 4).
// A: E = Q^T K  (Q,K hi/lo, 3-pass)
// softmax in D-fragments, P packed to bf16 in registers
// B: ao_part = P·V (per-warp 64-kv slice, single bf16, smem reduce)
// C: out = gamma*(Wo·ao + bo) + x  (ao hi/lo 2-pass)
// ===========================================================================
// smem bytes
#define AOF_Q2HI 0         // [128][17] u32 (aliased by ao2hi)
#define AOF_Q2LO 8704      // (aliased by ao2lo)
#define AOF_K2HI 17408     // [256][17] u32
#define AOF_K2LO 34816
#define AOF_V2   52224     // [32][132] u32
#define AOF_WO2  69120     // [256][17] u32
#define AOF_AOP  86528     // [8][64][33] float
#define AOF_RM   154112    // [128][5] float
#define AOF_RS   156672    // [128][5] float
#define ATTN_SMEM 159232

__global__ __launch_bounds__(256, 1)
void attn_mma_kernel(const float* __restrict__ Wo, const float* __restrict__ bo,
                     const float* __restrict__ gamma,
                     const float* __restrict__ x, float* __restrict__ out)
{
    extern __shared__ __align__(16) char smem[];
    uint32_t* Q2hi = (uint32_t*)(smem + AOF_Q2HI);
    uint32_t* Q2lo = (uint32_t*)(smem + AOF_Q2LO);
    uint32_t* K2hi = (uint32_t*)(smem + AOF_K2HI);
    uint32_t* K2lo = (uint32_t*)(smem + AOF_K2LO);
    uint32_t* V2   = (uint32_t*)(smem + AOF_V2);
    uint32_t* Wo2  = (uint32_t*)(smem + AOF_WO2);
    float*    AOP  = (float*)(smem + AOF_AOP);
    float*    RM   = (float*)(smem + AOF_RM);
    float*    RS   = (float*)(smem + AOF_RS);

    const int t = threadIdx.x;
    const int wid = t >> 5, lane = t & 31;
    const int g = lane >> 2, tig = lane & 3;
    const int warpM = wid >> 2, warpN = wid & 3;
    const int m0 = warpM * 64;
    const int n0 = warpN * 64;

    const int bid = blockIdx.x;
    const int b = bid >> 3;
    const int pixbase = (bid & 7) << 7;

    // ---- Phase 0: convert Q,K (hi/lo), V, Wo (bf16) into smem ----
    {
        const float* gq = g_q + (size_t)b * 32768;
        for (int item = t; item < 2048; item += 256) {
            int kp = item >> 7, pix = item & 127;
            float f0 = gq[(2 * kp) * 1024 + pixbase + pix];
            float f1 = gq[(2 * kp + 1) * 1024 + pixbase + pix];
            uint32_t hi = f2bf2(f0, f1);
            Q2hi[pix * 17 + kp] = hi;
            Q2lo[pix * 17 + kp] = f2bf2(f0 - bf_lo(hi), f1 - bf_hi(hi));
        }
        const float* gk = g_kp + (size_t)b * 8192;
        for (int item = t; item < 4096; item += 256) {
            int kp = item >> 8, kv = item & 255;
            float f0 = gk[(2 * kp) * 256 + kv];
            float f1 = gk[(2 * kp + 1) * 256 + kv];
            uint32_t hi = f2bf2(f0, f1);
            K2hi[kv * 17 + kp] = hi;
            K2lo[kv * 17 + kp] = f2bf2(f0 - bf_lo(hi), f1 - bf_hi(hi));
        }
        const float2* gv2 = (const float2*)(g_vp + (size_t)b * 8192);
        for (int item = t; item < 4096; item += 256) {
            int ch = item >> 7, kvp = item & 127;
            float2 f = gv2[ch * 128 + kvp];
            V2[ch * 132 + kvp] = f2bf2(f.x, f.y);
        }
        for (int item = t; item < 4096; item += 256) {
            int kp = item >> 8, o = item & 255;
            Wo2[o * 17 + kp] = f2bf2(Wo[o * 32 + 2 * kp], Wo[o * 32 + 2 * kp + 1]);
        }
    }
    __syncthreads();

    // ---- Stage A: E = Q^T K, hi/lo 3-pass. warp tile 64 pix x 64 kv ----
    float acc[4][8][4];
#pragma unroll
    for (int mt = 0; mt < 4; ++mt)
#pragma unroll
        for (int nt = 0; nt < 8; ++nt)
#pragma unroll
            for (int u = 0; u < 4; ++u) acc[mt][nt][u] = 0.f;

#pragma unroll
    for (int ks = 0; ks < 2; ++ks) {
        const int kk = ks * 8 + tig;
        uint32_t Ahi[4][4], Alo[4][4];
#pragma unroll
        for (int mt = 0; mt < 4; ++mt) {
            const int r0 = (m0 + mt * 16 + g) * 17;
            const int r8 = r0 + 8 * 17;
            Ahi[mt][0] = Q2hi[r0 + kk];  Ahi[mt][1] = Q2hi[r8 + kk];
            Ahi[mt][2] = Q2hi[r0 + kk + 4]; Ahi[mt][3] = Q2hi[r8 + kk + 4];
            Alo[mt][0] = Q2lo[r0 + kk];  Alo[mt][1] = Q2lo[r8 + kk];
            Alo[mt][2] = Q2lo[r0 + kk + 4]; Alo[mt][3] = Q2lo[r8 + kk + 4];
        }
#pragma unroll
        for (int nt = 0; nt < 8; ++nt) {
            const int col = (n0 + nt * 8 + g) * 17;
            uint32_t bh0 = K2hi[col + kk], bh1 = K2hi[col + kk + 4];
            uint32_t bl0 = K2lo[col + kk], bl1 = K2lo[col + kk + 4];
#pragma unroll
            for (int mt = 0; mt < 4; ++mt) {
                mma16816(acc[mt][nt], Ahi[mt], bh0, bh1);
                mma16816(acc[mt][nt], Ahi[mt], bl0, bl1);
                mma16816(acc[mt][nt], Alo[mt], bh0, bh1);
            }
        }
    }

    // ---- softmax: row max ----
#pragma unroll
    for (int mt = 0; mt < 4; ++mt) {
        float rA = -1e30f, rB = -1e30f;
#pragma unroll
        for (int nt = 0; nt < 8; ++nt) {
            rA = fmaxf(rA, fmaxf(acc[mt][nt][0], acc[mt][nt][1]));
            rB = fmaxf(rB, fmaxf(acc[mt][nt][2], acc[mt][nt][3]));
        }
        rA = fmaxf(rA, __shfl_xor_sync(0xffffffffu, rA, 1));
        rA = fmaxf(rA, __shfl_xor_sync(0xffffffffu, rA, 2));
        rB = fmaxf(rB, __shfl_xor_sync(0xffffffffu, rB, 1));
        rB = fmaxf(rB, __shfl_xor_sync(0xffffffffu, rB, 2));
        if (tig == 0) {
            RM[(m0 + mt * 16 + g) * 5 + warpN] = rA;
            RM[(m0 + mt * 16 + 8 + g) * 5 + warpN] = rB;
        }
    }
    __syncthreads();

    // ---- exp + pack P (registers) + row sums ----
    uint32_t P[4][8][2];
#pragma unroll
    for (int mt = 0; mt < 4; ++mt) {
        const int r = m0 + mt * 16 + g;
        const float mA = fmaxf(fmaxf(RM[r * 5 + 0], RM[r * 5 + 1]),
                               fmaxf(RM[r * 5 + 2], RM[r * 5 + 3]));
        const float mB = fmaxf(fmaxf(RM[(r + 8) * 5 + 0], RM[(r + 8) * 5 + 1]),
                               fmaxf(RM[(r + 8) * 5 + 2], RM[(r + 8) * 5 + 3]));
        float sA = 0.f, sB = 0.f;
#pragma unroll
        for (int nt = 0; nt < 8; ++nt) {
            float p0 = __expf(acc[mt][nt][0] - mA);
            float p1 = __expf(acc[mt][nt][1] - mA);
            float p2 = __expf(acc[mt][nt][2] - mB);
            float p3 = __expf(acc[mt][nt][3] - mB);
            sA += p0 + p1;
            sB += p2 + p3;
            P[mt][nt][0] = f2bf2(p0, p1);
            P[mt][nt][1] = f2bf2(p2, p3);
        }
        sA += __shfl_xor_sync(0xffffffffu, sA, 1);
        sA += __shfl_xor_sync(0xffffffffu, sA, 2);
        sB += __shfl_xor_sync(0xffffffffu, sB, 1);
        sB += __shfl_xor_sync(0xffffffffu, sB, 2);
        if (tig == 0) {
            RS[r * 5 + warpN] = sA;
            RS[(r + 8) * 5 + warpN] = sB;
        }
    }

    // ---- Stage B: partial ao = P·V over warp's 64-kv slice ----
    float aop[4][4][4];
#pragma unroll
    for (int mt = 0; mt < 4; ++mt)
#pragma unroll
        for (int n2 = 0; n2 < 4; ++n2)
#pragma unroll
            for (int u = 0; u < 4; ++u) aop[mt][n2][u] = 0.f;

#pragma unroll
    for (int kt = 0; kt < 4; ++kt) {
#pragma unroll
        for (int n2 = 0; n2 < 4; ++n2) {
            const int ch = n2 * 8 + g;
            uint32_t b0 = V2[ch * 132 + (n0 >> 1) + kt * 8 + tig];
            uint32_t b1 = V2[ch * 132 + (n0 >> 1) + kt * 8 + tig + 4];
#pragma unroll
            for (int mt = 0; mt < 4; ++mt) {
                uint32_t a[4] = {P[mt][2 * kt][0], P[mt][2 * kt][1],
                                 P[mt][2 * kt + 1][0], P[mt][2 * kt + 1][1]};
                mma16816(aop[mt][n2], a, b0, b1);
            }
        }
    }

    // store partials
    {
        float* aw = AOP + wid * (64 * 33);
#pragma unroll
        for (int mt = 0; mt < 4; ++mt) {
            const int pr = mt * 16 + g;
#pragma unroll
            for (int n2 = 0; n2 < 4; ++n2) {
                const int ch = n2 * 8 + 2 * tig;
                aw[pr * 33 + ch]     = aop[mt][n2][0];
                aw[pr * 33 + ch + 1] = aop[mt][n2][1];
                aw[(pr + 8) * 33 + ch]     = aop[mt][n2][2];
                aw[(pr + 8) * 33 + ch + 1] = aop[mt][n2][3];
            }
        }
    }
    __syncthreads();

    // ---- reduce partials, normalize, pack ao hi/lo into Q2 alias ----
    for (int item = t; item < 2048; item += 256) {
        const int pix = item >> 4, kp = item & 15;
        const int wm = pix >> 6, pl = pix & 63;
        const float inv = 1.f / (RS[pix * 5 + 0] + RS[pix * 5 + 1] +
                                 RS[pix * 5 + 2] + RS[pix * 5 + 3]);
        float s0 = 0.f, s1 = 0.f;
#pragma unroll
        for (int w = 0; w < 4; ++w) {
            const float* aw = AOP + (wm * 4 + w) * (64 * 33) + pl * 33;
            s0 += aw[2 * kp];
            s1 += aw[2 * kp + 1];
        }
        s0 *= inv; s1 *= inv;
        uint32_t hi = f2bf2(s0, s1);
        Q2hi[pix * 17 + kp] = hi;
        Q2lo[pix * 17 + kp] = f2bf2(s0 - bf_lo(hi), s1 - bf_hi(hi));
    }
    __syncthreads();

    // ---- Stage C: D = ao · Wo^T  (ao hi/lo 2-pass), + epilogue ----
#pragma unroll
    for (int mt = 0; mt < 4; ++mt)
#pragma unroll
        for (int nt = 0; nt < 8; ++nt)
#pragma unroll
            for (int u = 0; u < 4; ++u) acc[mt][nt][u] = 0.f;

#pragma unroll
    for (int ks = 0; ks < 2; ++ks) {
        const int kk = ks * 8 + tig;
        uint32_t Ahi[4][4], Alo[4][4];
#pragma unroll
        for (int mt = 0; mt < 4; ++mt) {
            const int r0 = (m0 + mt * 16 + g) * 17;
            const int r8 = r0 + 8 * 17;
            Ahi[mt][0] = Q2hi[r0 + kk];  Ahi[mt][1] = Q2hi[r8 + kk];
            Ahi[mt][2] = Q2hi[r0 + kk + 4]; Ahi[mt][3] = Q2hi[r8 + kk + 4];
            Alo[mt][0] = Q2lo[r0 + kk];  Alo[mt][1] = Q2lo[r8 + kk];
            Alo[mt][2] = Q2lo[r0 + kk + 4]; Alo[mt][3] = Q2lo[r8 + kk + 4];
        }
#pragma unroll
        for (int nt = 0; nt < 8; ++nt) {
            const int col = (n0 + nt * 8 + g) * 17;
            uint32_t b0 = Wo2[col + kk], b1 = Wo2[col + kk + 4];
#pragma unroll
            for (int mt = 0; mt < 4; ++mt) {
                mma16816(acc[mt][nt], Ahi[mt], b0, b1);
                mma16816(acc[mt][nt], Alo[mt], b0, b1);
            }
        }
    }

    // epilogue: out = gamma*(D + bo) + x
    {
        const float gam = __ldg(gamma);
        const int n = b >> 6, gy = (b >> 3) & 7, gx = b & 7;
        float bof[8][2];
#pragma unroll
        for (int nt = 0; nt < 8; ++nt) {
            const int o = n0 + nt * 8 + 2 * tig;
            bof[nt][0] = __ldg(bo + o);
            bof[nt][1] = __ldg(bo + o + 1);
        }
#pragma unroll
        for (int mt = 0; mt < 4; ++mt) {
            const int pl = m0 + mt * 16 + g;
            const int pg0 = pixbase + pl;
            const int i0 = pg0 >> 5, j0 = pg0 & 31;
            const size_t base0 = (size_t)n * (256 * 65536)
                               + (size_t)(gy * 32 + i0) * 256 + gx * 32 + j0;
#pragma unroll
            for (int nt = 0; nt < 8; ++nt) {
                const int o = n0 + nt * 8 + 2 * tig;
                const size_t a0 = base0 + (size_t)o * 65536;
                const size_t a1 = a0 + 65536;
                out[a0]     = fmaf(gam, acc[mt][nt][0] + bof[nt][0], x[a0]);
                out[a1]     = fmaf(gam, acc[mt][nt][1] + bof[nt][1], x[a1]);
                out[a0 + 8] = fmaf(gam, acc[mt][nt][2] + bof[nt][0], x[a0 + 8]);
                out[a1 + 8] = fmaf(gam, acc[mt][nt][3] + bof[nt][1], x[a1 + 8]);
            }
        }
    }
}

// ---------------------------------------------------------------------------
extern "C" void kernel_launch(void* const* d_in, const int* in_sizes, int n_in,
                              void* d_out, int out_size)
{
    const float* x  = (const float*)d_in[0];
    const float* Wq = (const float*)d_in[1];
    const float* bq = (const float*)d_in[2];
    const float* Wk = (const float*)d_in[3];
    const float* bk = (const float*)d_in[4];
    const float* Wv = (const float*)d_in[5];
    const float* bv = (const float*)d_in[6];
    const float* Wo = (const float*)d_in[7];
    const float* bo = (const float*)d_in[8];
    const float* gamma = (const float*)d_in[9];
    float* out = (float*)d_out;

    cudaFuncSetAttribute(qkv_mma_kernel, cudaFuncAttributeMaxDynamicSharedMemorySize, QKV_SMEM);
    cudaFuncSetAttribute(attn_mma_kernel, cudaFuncAttributeMaxDynamicSharedMemorySize, ATTN_SMEM);

    qkv_mma_kernel<<<2048, 256, QKV_SMEM>>>(x, Wq, bq, Wk, bk, Wv, bv);
    pool_kernel<<<8192, 256>>>();
    attn_mma_kernel<<<4096, 256, ATTN_SMEM>>>(Wo, bo, gamma, x, out);
}

// round 10
// speedup vs baseline: 4.6884x; 1.5154x over previous
#include <cuda_runtime.h>
#include <cuda_bf16.h>
#include <math.h>
#include <cstdint>

// Problem constants
#define NB 8
#define CIN 256
#define HW 65536
#define NCH 512
#define CQK 32
#define NQ 1024
#define NKV 256

// Scratch (device globals; no allocation allowed)
__device__ float g_q [(size_t)NCH * CQK * NQ];       // [b][ch][pix] fp32
__device__ float g_kf[(size_t)NCH * CQK * NQ];       // [b][ch][pix] fp32 (pre-pool)
__device__ float g_vf[(size_t)NCH * CQK * NQ];       // [b][ch][pix] fp32 (pre-pool)
__device__ uint32_t g_k2hi[(size_t)NCH * NKV * 20];  // [b][kv][20] bf16-pair hi
__device__ uint32_t g_k2lo[(size_t)NCH * NKV * 20];  // [b][kv][20] bf16-pair lo
__device__ uint32_t g_v2  [(size_t)NCH * 32 * 132];  // [b][ch][132] bf16 kv-pairs
__device__ uint32_t g_wo2 [256 * 20];                // [o][20] bf16 ch-pairs

// ===========================================================================
// helpers
// ===========================================================================
__device__ __forceinline__ uint32_t s2u32(const void* p) {
    uint32_t a;
    asm("{ .reg .u64 t; cvta.to.shared.u64 t, %1; cvt.u32.u64 %0, t; }" : "=r"(a) : "l"(p));
    return a;
}
__device__ __forceinline__ uint32_t f2bf2(float lo, float hi) {
    uint32_t r;
    asm("cvt.rn.bf16x2.f32 %0, %1, %2;" : "=r"(r) : "f"(hi), "f"(lo));
    return r;
}
__device__ __forceinline__ float bf_lo(uint32_t h) { return __uint_as_float(h << 16); }
__device__ __forceinline__ float bf_hi(uint32_t h) { return __uint_as_float(h & 0xffff0000u); }

__device__ __forceinline__ void mma16816(float* c, const uint32_t* a, uint32_t b0, uint32_t b1) {
    asm volatile(
        "mma.sync.aligned.m16n8k16.row.col.f32.bf16.bf16.f32 "
        "{%0,%1,%2,%3}, {%4,%5,%6,%7}, {%8,%9}, {%0,%1,%2,%3};"
        : "+f"(c[0]), "+f"(c[1]), "+f"(c[2]), "+f"(c[3])
        : "r"(a[0]), "r"(a[1]), "r"(a[2]), "r"(a[3]), "r"(b0), "r"(b1));
}

#define CP_ASYNC16(dst, src) \
    asm volatile("cp.async.ca.shared.global [%0], [%1], 16;" :: "r"(dst), "l"(src) : "memory")
#define CP_COMMIT() asm volatile("cp.async.commit_group;" ::: "memory")
#define CP_WAIT0()  asm volatile("cp.async.wait_group 0;" ::: "memory")

// ===========================================================================
// Kernel 1: q/k/v projection via mma.sync bf16 hi/lo 3-pass. (round-8, passing)
// ===========================================================================
#define OFF_W2HI  0
#define OFF_W2LO  50688
#define OFF_BIAS  101376
#define OFF_XS    101760
#define XS_FLOATS 8576
#define QKV_SMEM  170368

__global__ __launch_bounds__(256, 1)
void qkv_mma_kernel(const float* __restrict__ x,
                    const float* __restrict__ Wq, const float* __restrict__ bq,
                    const float* __restrict__ Wk, const float* __restrict__ bk,
                    const float* __restrict__ Wv, const float* __restrict__ bv)
{
    extern __shared__ __align__(16) char smem[];
    const uint32_t sbase = s2u32(smem);
    uint32_t* W2hi = (uint32_t*)(smem + OFF_W2HI);
    uint32_t* W2lo = (uint32_t*)(smem + OFF_W2LO);
    float*    bias = (float*)(smem + OFF_BIAS);
    float*    xsm  = (float*)(smem + OFF_XS);

    const int t = threadIdx.x;
    const int wid = t >> 5, lane = t & 31;
    const int g = lane >> 2, tig = lane & 3;
    const int warpM = wid >> 2, warpN = wid & 3;
    const int m0 = warpM * 48;
    const int n0w = warpN * 64;

    const int bid = blockIdx.x;
    const int h = bid & 255;
    const int n = bid >> 8;

    const float* xrow = x + (size_t)n * (256 * 65536) + (size_t)h * 256;

    {
        const uint32_t dstb = sbase + OFF_XS;
#pragma unroll
        for (int i = 0; i < 8; ++i) {
            int item = t + i * 256;
            int ch = item >> 6, p4 = item & 63;
            CP_ASYNC16(dstb + (uint32_t)(ch * 268 + p4 * 4) * 4,
                       xrow + (size_t)ch * 65536 + p4 * 4);
        }
        CP_COMMIT();
    }

    for (int item = t; item < 96 * 128; item += 256) {
        int m = item >> 7, kk = item & 127;
        const float* wrow = (m < 32) ? (Wq + m * 256)
                          : (m < 64) ? (Wk + (m - 32) * 256)
                                     : (Wv + (m - 64) * 256);
        float f0 = wrow[2 * kk], f1 = wrow[2 * kk + 1];
        uint32_t hi = f2bf2(f0, f1);
        uint32_t lo = f2bf2(f0 - bf_lo(hi), f1 - bf_hi(hi));
        W2hi[m * 132 + kk] = hi;
        W2lo[m * 132 + kk] = lo;
    }
    if (t < 96) bias[t] = (t < 32) ? bq[t] : (t < 64 ? bk[t - 32] : bv[t - 64]);

    float acc[3][8][4];
#pragma unroll
    for (int mt = 0; mt < 3; ++mt)
#pragma unroll
        for (int nt = 0; nt < 8; ++nt)
#pragma unroll
            for (int u = 0; u < 4; ++u) acc[mt][nt][u] = 0.f;

    CP_WAIT0();
    __syncthreads();

#pragma unroll 1
    for (int cc = 0; cc < 8; ++cc) {
        if (cc < 7) {
            const uint32_t dstb = sbase + OFF_XS + (uint32_t)(((cc + 1) & 1) * XS_FLOATS * 4);
            const float* srcb = xrow + (size_t)(cc + 1) * 32 * 65536;
#pragma unroll
            for (int i = 0; i < 8; ++i) {
                int item = t + i * 256;
                int ch = item >> 6, p4 = item & 63;
                CP_ASYNC16(dstb + (uint32_t)(ch * 268 + p4 * 4) * 4,
                           srcb + (size_t)ch * 65536 + p4 * 4);
            }
            CP_COMMIT();
        }

        const float* xsf = xsm + (cc & 1) * XS_FLOATS;
        const int kkc = cc * 16;

#pragma unroll
        for (int s = 0; s < 2; ++s) {
            const int ks = s * 16;
            const int kk0 = kkc + s * 8 + tig;

            uint32_t Ahi[3][4], Alo[3][4];
#pragma unroll
            for (int mt = 0; mt < 3; ++mt) {
                const int r0 = (m0 + mt * 16 + g) * 132;
                const int r8 = r0 + 8 * 132;
                Ahi[mt][0] = W2hi[r0 + kk0];
                Ahi[mt][1] = W2hi[r8 + kk0];
                Ahi[mt][2] = W2hi[r0 + kk0 + 4];
                Ahi[mt][3] = W2hi[r8 + kk0 + 4];
                Alo[mt][0] = W2lo[r0 + kk0];
                Alo[mt][1] = W2lo[r8 + kk0];
                Alo[mt][2] = W2lo[r0 + kk0 + 4];
                Alo[mt][3] = W2lo[r8 + kk0 + 4];
            }

#pragma unroll
            for (int nt = 0; nt < 8; ++nt) {
                const int base = (ks + 2 * tig) * 268 + n0w + nt * 8 + g;
                float x0 = xsf[base];
                float x1 = xsf[base + 268];
                float x2 = xsf[base + 8 * 268];
                float x3 = xsf[base + 9 * 268];
                uint32_t bhi0 = f2bf2(x0, x1);
                uint32_t bhi1 = f2bf2(x2, x3);
                uint32_t blo0 = f2bf2(x0 - bf_lo(bhi0), x1 - bf_hi(bhi0));
                uint32_t blo1 = f2bf2(x2 - bf_lo(bhi1), x3 - bf_hi(bhi1));
#pragma unroll
                for (int mt = 0; mt < 3; ++mt) {
                    mma16816(acc[mt][nt], Ahi[mt], bhi0, bhi1);
                    mma16816(acc[mt][nt], Ahi[mt], blo0, blo1);
                    mma16816(acc[mt][nt], Alo[mt], bhi0, bhi1);
                }
            }
        }

        if (cc < 7) CP_WAIT0();
        __syncthreads();
    }

    {
        const int gy = h >> 5, ii = h & 31;
#pragma unroll
        for (int mt = 0; mt < 3; ++mt) {
            const int mbase = m0 + mt * 16;
            const int aidx = mbase >> 5;
            float* arr = (aidx == 0) ? g_q : (aidx == 1) ? g_kf : g_vf;
            const int ch = (mbase & 31) + g;
            const float b1 = bias[mbase + g];
            const float b2 = bias[mbase + 8 + g];
#pragma unroll
            for (int nt = 0; nt < 8; ++nt) {
                const int w = n0w + nt * 8 + tig * 2;
                const int gx = w >> 5;
                const int b = n * 64 + gy * 8 + gx;
                const int pix = ii * 32 + (w & 31);
                float2* d0 = (float2*)(arr + ((size_t)(b * 32 + ch)) * 1024 + pix);
                float2* d1 = (float2*)(arr + ((size_t)(b * 32 + ch + 8)) * 1024 + pix);
                *d0 = make_float2(acc[mt][nt][0] + b1, acc[mt][nt][1] + b1);
                *d1 = make_float2(acc[mt][nt][2] + b2, acc[mt][nt][3] + b2);
            }
        }
    }
}

// ===========================================================================
// Kernel 2: pool + pack.  CTA b<512: stage chunk in smem, write
//  K: [256 kv][20] u32 bf16-pair hi/lo    V: [32 ch][132] u32 bf16 kv-pairs
// CTA 512: pack Wo -> g_wo2 [256][20]
// ===========================================================================
#define POOL_STRIDE 1028
#define POOL_SMEM  (32 * POOL_STRIDE * 4)

__global__ __launch_bounds__(256)
void pool_pack_kernel(const float* __restrict__ Wo)
{
    extern __shared__ float ps[];
    const int t = threadIdx.x;
    const int b = blockIdx.x;

    if (b < 512) {
        // ---- K ----
        const float4* src = (const float4*)(g_kf + (size_t)b * 32768);
        for (int i = t; i < 8192; i += 256) {
            int ch = i >> 8, p4 = i & 255;
            ((float4*)ps)[ch * 257 + p4] = src[i];
        }
        __syncthreads();
        for (int i = t; i < 4096; i += 256) {
            int kp = i & 15, kv = i >> 4;
            int pi = kv >> 4, pj = kv & 15;
            const float* r0 = ps + (2 * kp) * POOL_STRIDE + pi * 64 + 2 * pj;
            const float* r1 = r0 + POOL_STRIDE;
            float m0 = fmaxf(fmaxf(r0[0], r0[1]), fmaxf(r0[32], r0[33]));
            float m1 = fmaxf(fmaxf(r1[0], r1[1]), fmaxf(r1[32], r1[33]));
            uint32_t hi = f2bf2(m0, m1);
            uint32_t lo = f2bf2(m0 - bf_lo(hi), m1 - bf_hi(hi));
            g_k2hi[(size_t)b * 5120 + kv * 20 + kp] = hi;
            g_k2lo[(size_t)b * 5120 + kv * 20 + kp] = lo;
        }
        __syncthreads();
        // ---- V ----
        const float4* srcv = (const float4*)(g_vf + (size_t)b * 32768);
        for (int i = t; i < 8192; i += 256) {
            int ch = i >> 8, p4 = i & 255;
            ((float4*)ps)[ch * 257 + p4] = srcv[i];
        }
        __syncthreads();
        for (int i = t; i < 4096; i += 256) {
            int kvp = i & 127, ch = i >> 7;
            const float* rr = ps + ch * POOL_STRIDE;
            int kv0 = 2 * kvp, kv1 = kv0 + 1;
            int b0 = (kv0 >> 4) * 64 + 2 * (kv0 & 15);
            int b1i = (kv1 >> 4) * 64 + 2 * (kv1 & 15);
            float v0 = fmaxf(fmaxf(rr[b0], rr[b0 + 1]), fmaxf(rr[b0 + 32], rr[b0 + 33]));
            float v1 = fmaxf(fmaxf(rr[b1i], rr[b1i + 1]), fmaxf(rr[b1i + 32], rr[b1i + 33]));
            g_v2[(size_t)b * 4224 + ch * 132 + kvp] = f2bf2(v0, v1);
        }
    } else {
        for (int i = t; i < 4096; i += 256) {
            int kp = i & 15, o = i >> 4;
            g_wo2[o * 20 + kp] = f2bf2(Wo[o * 32 + 2 * kp], Wo[o * 32 + 2 * kp + 1]);
        }
    }
}

// ===========================================================================
// Kernel 3: attention on mma.sync, overhead-stripped.
// 256 threads = 8 warps. Stage A: warpM2 x warpN4, 64pix x 32kv per half,
// 2 kv halves, no-max softmax, P bf16 -> smem. Stage B: warp = 16 pix x 256 kv
// (no cross-warp reduce). ao normalized + packed in regs -> Stage C.
// ===========================================================================
#define AOF_Q2HI 0          // [128][20] u32
#define AOF_Q2LO 10240
#define AOF_K2HI 20480      // [256][20] u32
#define AOF_K2LO 40960
#define AOF_P2   61440      // [128][132] u32 (bf16 kv-pairs)
#define AOF_V2   129024     // [32][132] u32
#define AOF_WO2  145920     // [256][20] u32
#define AOF_RS   166400     // [128][5] float
#define ATTN_SMEM 168960

__global__ __launch_bounds__(256, 1)
void attn_mma_kernel(const float* __restrict__ bo,
                     const float* __restrict__ gamma,
                     const float* __restrict__ x, float* __restrict__ out)
{
    extern __shared__ __align__(16) char smem[];
    const uint32_t sbase = s2u32(smem);
    uint32_t* Q2hi = (uint32_t*)(smem + AOF_Q2HI);
    uint32_t* Q2lo = (uint32_t*)(smem + AOF_Q2LO);
    uint32_t* K2hi = (uint32_t*)(smem + AOF_K2HI);
    uint32_t* K2lo = (uint32_t*)(smem + AOF_K2LO);
    uint32_t* P2   = (uint32_t*)(smem + AOF_P2);
    uint32_t* V2   = (uint32_t*)(smem + AOF_V2);
    uint32_t* Wo2  = (uint32_t*)(smem + AOF_WO2);
    float*    RS   = (float*)(smem + AOF_RS);

    const int t = threadIdx.x;
    const int wid = t >> 5, lane = t & 31;
    const int g = lane >> 2, tig = lane & 3;
    const int warpM = wid >> 2, warpN = wid & 3;
    const int m0 = warpM * 64;

    const int bid = blockIdx.x;
    const int b = bid >> 3;
    const int pixbase = (bid & 7) << 7;

    // ---- Phase 0: cp.async K2/V2/Wo2, convert Q ----
    for (int c = t; c < 1024; c += 256) {
        int row = c >> 2, part = c & 3;
        CP_ASYNC16(sbase + AOF_K2HI + row * 80 + part * 16,
                   g_k2hi + (size_t)b * 5120 + row * 20 + part * 4);
        CP_ASYNC16(sbase + AOF_K2LO + row * 80 + part * 16,
                   g_k2lo + (size_t)b * 5120 + row * 20 + part * 4);
        CP_ASYNC16(sbase + AOF_WO2 + row * 80 + part * 16,
                   g_wo2 + row * 20 + part * 4);
    }
    for (int c = t; c < 1056; c += 256)
        CP_ASYNC16(sbase + AOF_V2 + c * 16, g_v2 + (size_t)b * 4224 + c * 4);
    CP_COMMIT();

    {
        const float* gq = g_q + (size_t)b * 32768;
        for (int item = t; item < 2048; item += 256) {
            int kp = item >> 7, pix = item & 127;
            float f0 = gq[(2 * kp) * 1024 + pixbase + pix];
            float f1 = gq[(2 * kp + 1) * 1024 + pixbase + pix];
            uint32_t hi = f2bf2(f0, f1);
            Q2hi[pix * 20 + kp] = hi;
            Q2lo[pix * 20 + kp] = f2bf2(f0 - bf_lo(hi), f1 - bf_hi(hi));
        }
    }
    CP_WAIT0();
    __syncthreads();

    // ---- Stage A: E = Q^T K (3-pass), no-max exp, P -> smem, row sums ----
    float sA[4], sB[4];
#pragma unroll
    for (int mt = 0; mt < 4; ++mt) { sA[mt] = 0.f; sB[mt] = 0.f; }

#pragma unroll
    for (int kvh = 0; kvh < 2; ++kvh) {
        float acc[4][4][4];
#pragma unroll
        for (int mt = 0; mt < 4; ++mt)
#pragma unroll
            for (int nt = 0; nt < 4; ++nt)
#pragma unroll
                for (int u = 0; u < 4; ++u) acc[mt][nt][u] = 0.f;

#pragma unroll
        for (int ks = 0; ks < 2; ++ks) {
            const int kk = ks * 8 + tig;
            uint32_t Ahi[4][4], Alo[4][4];
#pragma unroll
            for (int mt = 0; mt < 4; ++mt) {
                const int r0 = (m0 + mt * 16 + g) * 20;
                const int r8 = r0 + 8 * 20;
                Ahi[mt][0] = Q2hi[r0 + kk];  Ahi[mt][1] = Q2hi[r8 + kk];
                Ahi[mt][2] = Q2hi[r0 + kk + 4]; Ahi[mt][3] = Q2hi[r8 + kk + 4];
                Alo[mt][0] = Q2lo[r0 + kk];  Alo[mt][1] = Q2lo[r8 + kk];
                Alo[mt][2] = Q2lo[r0 + kk + 4]; Alo[mt][3] = Q2lo[r8 + kk + 4];
            }
#pragma unroll
            for (int nt = 0; nt < 4; ++nt) {
                const int col = (kvh * 128 + warpN * 32 + nt * 8 + g) * 20;
                uint32_t bh0 = K2hi[col + kk], bh1 = K2hi[col + kk + 4];
                uint32_t bl0 = K2lo[col + kk], bl1 = K2lo[col + kk + 4];
#pragma unroll
                for (int mt = 0; mt < 4; ++mt) {
                    mma16816(acc[mt][nt], Ahi[mt], bh0, bh1);
                    mma16816(acc[mt][nt], Ahi[mt], bl0, bl1);
                    mma16816(acc[mt][nt], Alo[mt], bh0, bh1);
                }
            }
        }

        // exp (no max subtraction) + pack P + accumulate row sums
#pragma unroll
        for (int mt = 0; mt < 4; ++mt) {
            const int rowA = (m0 + mt * 16 + g) * 132;
            const int rowB = rowA + 8 * 132;
#pragma unroll
            for (int nt = 0; nt < 4; ++nt) {
                float p0 = __expf(acc[mt][nt][0]);
                float p1 = __expf(acc[mt][nt][1]);
                float p2 = __expf(acc[mt][nt][2]);
                float p3 = __expf(acc[mt][nt][3]);
                sA[mt] += p0 + p1;
                sB[mt] += p2 + p3;
                const int colu = kvh * 64 + warpN * 16 + nt * 4 + tig;
                P2[rowA + colu] = f2bf2(p0, p1);
                P2[rowB + colu] = f2bf2(p2, p3);
            }
        }
    }

#pragma unroll
    for (int mt = 0; mt < 4; ++mt) {
        float a = sA[mt], bx = sB[mt];
        a += __shfl_xor_sync(0xffffffffu, a, 1);
        a += __shfl_xor_sync(0xffffffffu, a, 2);
        bx += __shfl_xor_sync(0xffffffffu, bx, 1);
        bx += __shfl_xor_sync(0xffffffffu, bx, 2);
        if (tig == 0) {
            RS[(m0 + mt * 16 + g) * 5 + warpN] = a;
            RS[(m0 + mt * 16 + 8 + g) * 5 + warpN] = bx;
        }
    }
    __syncthreads();

    // ---- Stage B: warp owns 16 pix x 32 ch over full 256 kv ----
    const int m0b = wid * 16;
    float accB[4][4];
#pragma unroll
    for (int n2 = 0; n2 < 4; ++n2)
#pragma unroll
        for (int u = 0; u < 4; ++u) accB[n2][u] = 0.f;

#pragma unroll
    for (int kt = 0; kt < 16; ++kt) {
        uint32_t a[4];
        a[0] = P2[(m0b + g) * 132 + kt * 8 + tig];
        a[1] = P2[(m0b + 8 + g) * 132 + kt * 8 + tig];
        a[2] = P2[(m0b + g) * 132 + kt * 8 + 4 + tig];
        a[3] = P2[(m0b + 8 + g) * 132 + kt * 8 + 4 + tig];
#pragma unroll
        for (int n2 = 0; n2 < 4; ++n2) {
            uint32_t b0 = V2[(n2 * 8 + g) * 132 + kt * 8 + tig];
            uint32_t b1 = V2[(n2 * 8 + g) * 132 + kt * 8 + 4 + tig];
            mma16816(accB[n2], a, b0, b1);
        }
    }

    // normalize + pack ao into stage-C A fragments (registers only)
    uint32_t aoHi[2][4], aoLo[2][4];
    {
        const int rA = (m0b + g) * 5, rB = (m0b + 8 + g) * 5;
        const float invA = 1.f / (RS[rA] + RS[rA + 1] + RS[rA + 2] + RS[rA + 3]);
        const float invB = 1.f / (RS[rB] + RS[rB + 1] + RS[rB + 2] + RS[rB + 3]);
#pragma unroll
        for (int ks = 0; ks < 2; ++ks) {
            const int n2a = ks * 2, n2b = ks * 2 + 1;
            float a0 = accB[n2a][0] * invA, a1 = accB[n2a][1] * invA;
            float a2 = accB[n2a][2] * invB, a3 = accB[n2a][3] * invB;
            float a4 = accB[n2b][0] * invA, a5 = accB[n2b][1] * invA;
            float a6 = accB[n2b][2] * invB, a7 = accB[n2b][3] * invB;
            aoHi[ks][0] = f2bf2(a0, a1);
            aoHi[ks][1] = f2bf2(a2, a3);
            aoHi[ks][2] = f2bf2(a4, a5);
            aoHi[ks][3] = f2bf2(a6, a7);
            aoLo[ks][0] = f2bf2(a0 - bf_lo(aoHi[ks][0]), a1 - bf_hi(aoHi[ks][0]));
            aoLo[ks][1] = f2bf2(a2 - bf_lo(aoHi[ks][1]), a3 - bf_hi(aoHi[ks][1]));
            aoLo[ks][2] = f2bf2(a4 - bf_lo(aoHi[ks][2]), a5 - bf_hi(aoHi[ks][2]));
            aoLo[ks][3] = f2bf2(a6 - bf_lo(aoHi[ks][3]), a7 - bf_hi(aoHi[ks][3]));
        }
    }

    // ---- Stage C: out rows (16 pix) x 256 o, in two o-halves ----
    const float gam = __ldg(gamma);
    const int n = b >> 6, gy = (b >> 3) & 7, gx = b & 7;
    const int pl0 = m0b + g;
    const int pg0 = pixbase + pl0;
    const int i0 = pg0 >> 5, j0 = pg0 & 31;
    const size_t base0 = (size_t)n * (256 * 65536)
                       + (size_t)(gy * 32 + i0) * 256 + gx * 32 + j0;

#pragma unroll 1
    for (int hh = 0; hh < 2; ++hh) {
        float acc2[16][4];
#pragma unroll
        for (int nt = 0; nt < 16; ++nt)
#pragma unroll
            for (int u = 0; u < 4; ++u) acc2[nt][u] = 0.f;

#pragma unroll
        for (int ks = 0; ks < 2; ++ks) {
            const int kk = ks * 8 + tig;
#pragma unroll
            for (int nt = 0; nt < 16; ++nt) {
                const int col = (hh * 128 + nt * 8 + g) * 20;
                uint32_t b0 = Wo2[col + kk], b1 = Wo2[col + kk + 4];
                mma16816(acc2[nt], aoHi[ks], b0, b1);
                mma16816(acc2[nt], aoLo[ks], b0, b1);
            }
        }

#pragma unroll
        for (int nt = 0; nt < 16; ++nt) {
            const int o = hh * 128 + nt * 8 + 2 * tig;
            const float bo0 = __ldg(bo + o);
            const float bo1 = __ldg(bo + o + 1);
            const size_t a0 = base0 + (size_t)o * 65536;
            const size_t a1 = a0 + 65536;
            out[a0]     = fmaf(gam, acc2[nt][0] + bo0, x[a0]);
            out[a1]     = fmaf(gam, acc2[nt][1] + bo1, x[a1]);
            out[a0 + 8] = fmaf(gam, acc2[nt][2] + bo0, x[a0 + 8]);
            out[a1 + 8] = fmaf(gam, acc2[nt][3] + bo1, x[a1 + 8]);
        }
    }
}

// ---------------------------------------------------------------------------
extern "C" void kernel_launch(void* const* d_in, const int* in_sizes, int n_in,
                              void* d_out, int out_size)
{
    const float* x  = (const float*)d_in[0];
    const float* Wq = (const float*)d_in[1];
    const float* bq = (const float*)d_in[2];
    const float* Wk = (const float*)d_in[3];
    const float* bk = (const float*)d_in[4];
    const float* Wv = (const float*)d_in[5];
    const float* bv = (const float*)d_in[6];
    const float* Wo = (const float*)d_in[7];
    const float* bo = (const float*)d_in[8];
    const float* gamma = (const float*)d_in[9];
    float* out = (float*)d_out;

    cudaFuncSetAttribute(qkv_mma_kernel, cudaFuncAttributeMaxDynamicSharedMemorySize, QKV_SMEM);
    cudaFuncSetAttribute(pool_pack_kernel, cudaFuncAttributeMaxDynamicSharedMemorySize, POOL_SMEM);
    cudaFuncSetAttribute(attn_mma_kernel, cudaFuncAttributeMaxDynamicSharedMemorySize, ATTN_SMEM);

    qkv_mma_kernel<<<2048, 256, QKV_SMEM>>>(x, Wq, bq, Wk, bk, Wv, bv);
    pool_pack_kernel<<<513, 256, POOL_SMEM>>>(Wo);
    attn_mma_kernel<<<4096, 256, ATTN_SMEM>>>(bo, gamma, x, out);
}

// round 12
// speedup vs baseline: 5.1141x; 1.0908x over previous
#include <cuda_runtime.h>
#include <cuda_bf16.h>
#include <math.h>
#include <cstdint>

// Problem constants
#define NB 8
#define CIN 256
#define HW 65536
#define NCH 512
#define CQK 32
#define NQ 1024
#define NKV 256

// Scratch (device globals; no allocation allowed)
__device__ float g_q [(size_t)NCH * CQK * NQ];       // [b][ch][pix] fp32
__device__ float g_kf[(size_t)NCH * CQK * NQ];       // [b][ch][pix] fp32 (pre-pool)
__device__ float g_vf[(size_t)NCH * CQK * NQ];       // [b][ch][pix] fp32 (pre-pool)
__device__ uint32_t g_k2hi[(size_t)NCH * NKV * 20];  // [b][kv][20] bf16-pair hi
__device__ uint32_t g_k2lo[(size_t)NCH * NKV * 20];  // [b][kv][20] bf16-pair lo
__device__ uint32_t g_v2  [(size_t)NCH * 32 * 132];  // [b][ch][132] bf16 kv-pairs
__device__ uint32_t g_wo2 [256 * 20];                // [o][20] bf16 ch-pairs

// ===========================================================================
// helpers
// ===========================================================================
__device__ __forceinline__ uint32_t s2u32(const void* p) {
    uint32_t a;
    asm("{ .reg .u64 t; cvta.to.shared.u64 t, %1; cvt.u32.u64 %0, t; }" : "=r"(a) : "l"(p));
    return a;
}
__device__ __forceinline__ uint32_t f2bf2(float lo, float hi) {
    uint32_t r;
    asm("cvt.rn.bf16x2.f32 %0, %1, %2;" : "=r"(r) : "f"(hi), "f"(lo));
    return r;
}
__device__ __forceinline__ float bf_lo(uint32_t h) { return __uint_as_float(h << 16); }
__device__ __forceinline__ float bf_hi(uint32_t h) { return __uint_as_float(h & 0xffff0000u); }

__device__ __forceinline__ void mma16816(float* c, const uint32_t* a, uint32_t b0, uint32_t b1) {
    asm volatile(
        "mma.sync.aligned.m16n8k16.row.col.f32.bf16.bf16.f32 "
        "{%0,%1,%2,%3}, {%4,%5,%6,%7}, {%8,%9}, {%0,%1,%2,%3};"
        : "+f"(c[0]), "+f"(c[1]), "+f"(c[2]), "+f"(c[3])
        : "r"(a[0]), "r"(a[1]), "r"(a[2]), "r"(a[3]), "r"(b0), "r"(b1));
}

#define CP_ASYNC16(dst, src) \
    asm volatile("cp.async.ca.shared.global [%0], [%1], 16;" :: "r"(dst), "l"(src) : "memory")
#define CP_COMMIT() asm volatile("cp.async.commit_group;" ::: "memory")
#define CP_WAIT0()  asm volatile("cp.async.wait_group 0;" ::: "memory")

// ===========================================================================
// Kernel 1: q/k/v projection via mma.sync bf16 hi/lo 3-pass.
// 512 threads = 16 warps: warpM(2, 48 rows) x warpN(8, 32 px). K=256.
// ===========================================================================
#define OFF_W2HI  0
#define OFF_W2LO  50688
#define OFF_BIAS  101376
#define OFF_XS    101760
#define XS_FLOATS 8576
#define QKV_SMEM  170368

__global__ __launch_bounds__(512, 1)
void qkv_mma_kernel(const float* __restrict__ x,
                    const float* __restrict__ Wq, const float* __restrict__ bq,
                    const float* __restrict__ Wk, const float* __restrict__ bk,
                    const float* __restrict__ Wv, const float* __restrict__ bv)
{
    extern __shared__ __align__(16) char smem[];
    const uint32_t sbase = s2u32(smem);
    uint32_t* W2hi = (uint32_t*)(smem + OFF_W2HI);
    uint32_t* W2lo = (uint32_t*)(smem + OFF_W2LO);
    float*    bias = (float*)(smem + OFF_BIAS);
    float*    xsm  = (float*)(smem + OFF_XS);

    const int t = threadIdx.x;
    const int wid = t >> 5, lane = t & 31;
    const int g = lane >> 2, tig = lane & 3;
    const int warpM = wid >> 3, warpN = wid & 7;
    const int m0 = warpM * 48;
    const int n0w = warpN * 32;

    const int bid = blockIdx.x;
    const int h = bid & 255;
    const int n = bid >> 8;

    const float* xrow = x + (size_t)n * (256 * 65536) + (size_t)h * 256;

    {
        const uint32_t dstb = sbase + OFF_XS;
#pragma unroll
        for (int i = 0; i < 4; ++i) {
            int item = t + i * 512;
            int ch = item >> 6, p4 = item & 63;
            CP_ASYNC16(dstb + (uint32_t)(ch * 268 + p4 * 4) * 4,
                       xrow + (size_t)ch * 65536 + p4 * 4);
        }
        CP_COMMIT();
    }

    for (int item = t; item < 96 * 128; item += 512) {
        int m = item >> 7, kk = item & 127;
        const float* wrow = (m < 32) ? (Wq + m * 256)
                          : (m < 64) ? (Wk + (m - 32) * 256)
                                     : (Wv + (m - 64) * 256);
        float f0 = wrow[2 * kk], f1 = wrow[2 * kk + 1];
        uint32_t hi = f2bf2(f0, f1);
        uint32_t lo = f2bf2(f0 - bf_lo(hi), f1 - bf_hi(hi));
        W2hi[m * 132 + kk] = hi;
        W2lo[m * 132 + kk] = lo;
    }
    if (t < 96) bias[t] = (t < 32) ? bq[t] : (t < 64 ? bk[t - 32] : bv[t - 64]);

    float acc[3][4][4];
#pragma unroll
    for (int mt = 0; mt < 3; ++mt)
#pragma unroll
        for (int nt = 0; nt < 4; ++nt)
#pragma unroll
            for (int u = 0; u < 4; ++u) acc[mt][nt][u] = 0.f;

    CP_WAIT0();
    __syncthreads();

#pragma unroll 1
    for (int cc = 0; cc < 8; ++cc) {
        if (cc < 7) {
            const uint32_t dstb = sbase + OFF_XS + (uint32_t)(((cc + 1) & 1) * XS_FLOATS * 4);
            const float* srcb = xrow + (size_t)(cc + 1) * 32 * 65536;
#pragma unroll
            for (int i = 0; i < 4; ++i) {
                int item = t + i * 512;
                int ch = item >> 6, p4 = item & 63;
                CP_ASYNC16(dstb + (uint32_t)(ch * 268 + p4 * 4) * 4,
                           srcb + (size_t)ch * 65536 + p4 * 4);
            }
            CP_COMMIT();
        }

        const float* xsf = xsm + (cc & 1) * XS_FLOATS;
        const int kkc = cc * 16;

#pragma unroll
        for (int s = 0; s < 2; ++s) {
            const int ks = s * 16;
            const int kk0 = kkc + s * 8 + tig;

            uint32_t Ahi[3][4], Alo[3][4];
#pragma unroll
            for (int mt = 0; mt < 3; ++mt) {
                const int r0 = (m0 + mt * 16 + g) * 132;
                const int r8 = r0 + 8 * 132;
                Ahi[mt][0] = W2hi[r0 + kk0];
                Ahi[mt][1] = W2hi[r8 + kk0];
                Ahi[mt][2] = W2hi[r0 + kk0 + 4];
                Ahi[mt][3] = W2hi[r8 + kk0 + 4];
                Alo[mt][0] = W2lo[r0 + kk0];
                Alo[mt][1] = W2lo[r8 + kk0];
                Alo[mt][2] = W2lo[r0 + kk0 + 4];
                Alo[mt][3] = W2lo[r8 + kk0 + 4];
            }

#pragma unroll
            for (int nt = 0; nt < 4; ++nt) {
                const int base = (ks + 2 * tig) * 268 + n0w + nt * 8 + g;
                float x0 = xsf[base];
                float x1 = xsf[base + 268];
                float x2 = xsf[base + 8 * 268];
                float x3 = xsf[base + 9 * 268];
                uint32_t bhi0 = f2bf2(x0, x1);
                uint32_t bhi1 = f2bf2(x2, x3);
                uint32_t blo0 = f2bf2(x0 - bf_lo(bhi0), x1 - bf_hi(bhi0));
                uint32_t blo1 = f2bf2(x2 - bf_lo(bhi1), x3 - bf_hi(bhi1));
#pragma unroll
                for (int mt = 0; mt < 3; ++mt) {
                    mma16816(acc[mt][nt], Ahi[mt], bhi0, bhi1);
                    mma16816(acc[mt][nt], Ahi[mt], blo0, blo1);
                    mma16816(acc[mt][nt], Alo[mt], bhi0, bhi1);
                }
            }
        }

        if (cc < 7) CP_WAIT0();
        __syncthreads();
    }

    {
        const int gy = h >> 5, ii = h & 31;
#pragma unroll
        for (int mt = 0; mt < 3; ++mt) {
            const int mbase = m0 + mt * 16;
            const int aidx = mbase >> 5;
            float* arr = (aidx == 0) ? g_q : (aidx == 1) ? g_kf : g_vf;
            const int ch = (mbase & 31) + g;
            const float b1 = bias[mbase + g];
            const float b2 = bias[mbase + 8 + g];
#pragma unroll
            for (int nt = 0; nt < 4; ++nt) {
                const int w = n0w + nt * 8 + tig * 2;
                const int gx = w >> 5;
                const int b = n * 64 + gy * 8 + gx;
                const int pix = ii * 32 + (w & 31);
                float2* d0 = (float2*)(arr + ((size_t)(b * 32 + ch)) * 1024 + pix);
                float2* d1 = (float2*)(arr + ((size_t)(b * 32 + ch + 8)) * 1024 + pix);
                *d0 = make_float2(acc[mt][nt][0] + b1, acc[mt][nt][1] + b1);
                *d1 = make_float2(acc[mt][nt][2] + b2, acc[mt][nt][3] + b2);
            }
        }
    }
}

// ===========================================================================
// Kernel 2: pool + pack (unchanged from round 10, passing)
// ===========================================================================
#define POOL_STRIDE 1028
#define POOL_SMEM  (32 * POOL_STRIDE * 4)

__global__ __launch_bounds__(256)
void pool_pack_kernel(const float* __restrict__ Wo)
{
    extern __shared__ float ps[];
    const int t = threadIdx.x;
    const int b = blockIdx.x;

    if (b < 512) {
        const float4* src = (const float4*)(g_kf + (size_t)b * 32768);
        for (int i = t; i < 8192; i += 256) {
            int ch = i >> 8, p4 = i & 255;
            ((float4*)ps)[ch * 257 + p4] = src[i];
        }
        __syncthreads();
        for (int i = t; i < 4096; i += 256) {
            int kp = i & 15, kv = i >> 4;
            int pi = kv >> 4, pj = kv & 15;
            const float* r0 = ps + (2 * kp) * POOL_STRIDE + pi * 64 + 2 * pj;
            const float* r1 = r0 + POOL_STRIDE;
            float m0 = fmaxf(fmaxf(r0[0], r0[1]), fmaxf(r0[32], r0[33]));
            float m1 = fmaxf(fmaxf(r1[0], r1[1]), fmaxf(r1[32], r1[33]));
            uint32_t hi = f2bf2(m0, m1);
            uint32_t lo = f2bf2(m0 - bf_lo(hi), m1 - bf_hi(hi));
            g_k2hi[(size_t)b * 5120 + kv * 20 + kp] = hi;
            g_k2lo[(size_t)b * 5120 + kv * 20 + kp] = lo;
        }
        __syncthreads();
        const float4* srcv = (const float4*)(g_vf + (size_t)b * 32768);
        for (int i = t; i < 8192; i += 256) {
            int ch = i >> 8, p4 = i & 255;
            ((float4*)ps)[ch * 257 + p4] = srcv[i];
        }
        __syncthreads();
        for (int i = t; i < 4096; i += 256) {
            int kvp = i & 127, ch = i >> 7;
            const float* rr = ps + ch * POOL_STRIDE;
            int kv0 = 2 * kvp, kv1 = kv0 + 1;
            int b0 = (kv0 >> 4) * 64 + 2 * (kv0 & 15);
            int b1i = (kv1 >> 4) * 64 + 2 * (kv1 & 15);
            float v0 = fmaxf(fmaxf(rr[b0], rr[b0 + 1]), fmaxf(rr[b0 + 32], rr[b0 + 33]));
            float v1 = fmaxf(fmaxf(rr[b1i], rr[b1i + 1]), fmaxf(rr[b1i + 32], rr[b1i + 33]));
            g_v2[(size_t)b * 4224 + ch * 132 + kvp] = f2bf2(v0, v1);
        }
    } else {
        for (int i = t; i < 4096; i += 256) {
            int kp = i & 15, o = i >> 4;
            g_wo2[o * 20 + kp] = f2bf2(Wo[o * 32 + 2 * kp], Wo[o * 32 + 2 * kp + 1]);
        }
    }
}

// ===========================================================================
// Kernel 3: attention on mma.sync, 512 threads = 16 warps.
// A: warpM(2,64px) x warpN(8,32kv). B: 8 px-groups x 2 kv-halves, fp32
// partials in dead-K smem. C: warp = 16 px x 128 o.
// ===========================================================================
#define AOF_Q2HI 0          // [128][20] u32 (aliased by ao2hi)
#define AOF_Q2LO 10240      // (aliased by ao2lo)
#define AOF_K2HI 20480      // [256][20] u32  (aliased by AOP after stage A)
#define AOF_K2LO 40960
#define AOF_P2   61440      // [128][132] u32 (bf16 kv-pairs)
#define AOF_V2   129024     // [32][132] u32
#define AOF_WO2  145920     // [256][20] u32
#define AOF_RS   166400     // [128][9] float
#define ATTN_SMEM 171008

__global__ __launch_bounds__(512, 1)
void attn_mma_kernel(const float* __restrict__ bo,
                     const float* __restrict__ gamma,
                     const float* __restrict__ x, float* __restrict__ out)
{
    extern __shared__ __align__(16) char smem[];
    const uint32_t sbase = s2u32(smem);
    uint32_t* Q2hi = (uint32_t*)(smem + AOF_Q2HI);
    uint32_t* Q2lo = (uint32_t*)(smem + AOF_Q2LO);
    uint32_t* K2hi = (uint32_t*)(smem + AOF_K2HI);
    uint32_t* K2lo = (uint32_t*)(smem + AOF_K2LO);
    uint32_t* P2   = (uint32_t*)(smem + AOF_P2);
    uint32_t* V2   = (uint32_t*)(smem + AOF_V2);
    uint32_t* Wo2  = (uint32_t*)(smem + AOF_WO2);
    float*    RS   = (float*)(smem + AOF_RS);
    float*    AOP  = (float*)(smem + AOF_K2HI);   // [2][128][34] alias (K dead)

    const int t = threadIdx.x;
    const int wid = t >> 5, lane = t & 31;
    const int g = lane >> 2, tig = lane & 3;

    const int bid = blockIdx.x;
    const int b = bid >> 3;
    const int pixbase = (bid & 7) << 7;

    // ---- Phase 0: cp.async K2/V2/Wo2, convert Q ----
    for (int c = t; c < 1024; c += 512) {
        int row = c >> 2, part = c & 3;
        CP_ASYNC16(sbase + AOF_K2HI + row * 80 + part * 16,
                   g_k2hi + (size_t)b * 5120 + row * 20 + part * 4);
        CP_ASYNC16(sbase + AOF_K2LO + row * 80 + part * 16,
                   g_k2lo + (size_t)b * 5120 + row * 20 + part * 4);
        CP_ASYNC16(sbase + AOF_WO2 + row * 80 + part * 16,
                   g_wo2 + row * 20 + part * 4);
    }
    for (int c = t; c < 1056; c += 512)
        CP_ASYNC16(sbase + AOF_V2 + c * 16, g_v2 + (size_t)b * 4224 + c * 4);
    CP_COMMIT();

    {
        const float* gq = g_q + (size_t)b * 32768;
        for (int item = t; item < 2048; item += 512) {
            int kp = item >> 7, pix = item & 127;
            float f0 = gq[(2 * kp) * 1024 + pixbase + pix];
            float f1 = gq[(2 * kp + 1) * 1024 + pixbase + pix];
            uint32_t hi = f2bf2(f0, f1);
            Q2hi[pix * 20 + kp] = hi;
            Q2lo[pix * 20 + kp] = f2bf2(f0 - bf_lo(hi), f1 - bf_hi(hi));
        }
    }
    CP_WAIT0();
    __syncthreads();

    // ---- Stage A: E = Q^T K (3-pass), no-max exp, P -> smem, row sums ----
    {
        const int warpM = wid >> 3, warpN = wid & 7;
        const int m0 = warpM * 64;
        float acc[4][4][4];
#pragma unroll
        for (int mt = 0; mt < 4; ++mt)
#pragma unroll
            for (int nt = 0; nt < 4; ++nt)
#pragma unroll
                for (int u = 0; u < 4; ++u) acc[mt][nt][u] = 0.f;

#pragma unroll
        for (int ks = 0; ks < 2; ++ks) {
            const int kk = ks * 8 + tig;
            uint32_t Ahi[4][4], Alo[4][4];
#pragma unroll
            for (int mt = 0; mt < 4; ++mt) {
                const int r0 = (m0 + mt * 16 + g) * 20;
                const int r8 = r0 + 8 * 20;
                Ahi[mt][0] = Q2hi[r0 + kk];  Ahi[mt][1] = Q2hi[r8 + kk];
                Ahi[mt][2] = Q2hi[r0 + kk + 4]; Ahi[mt][3] = Q2hi[r8 + kk + 4];
                Alo[mt][0] = Q2lo[r0 + kk];  Alo[mt][1] = Q2lo[r8 + kk];
                Alo[mt][2] = Q2lo[r0 + kk + 4]; Alo[mt][3] = Q2lo[r8 + kk + 4];
            }
#pragma unroll
            for (int nt = 0; nt < 4; ++nt) {
                const int col = (warpN * 32 + nt * 8 + g) * 20;
                uint32_t bh0 = K2hi[col + kk], bh1 = K2hi[col + kk + 4];
                uint32_t bl0 = K2lo[col + kk], bl1 = K2lo[col + kk + 4];
#pragma unroll
                for (int mt = 0; mt < 4; ++mt) {
                    mma16816(acc[mt][nt], Ahi[mt], bh0, bh1);
                    mma16816(acc[mt][nt], Ahi[mt], bl0, bl1);
                    mma16816(acc[mt][nt], Alo[mt], bh0, bh1);
                }
            }
        }

        // exp (no max) + pack P + row sums
#pragma unroll
        for (int mt = 0; mt < 4; ++mt) {
            const int rowA = (m0 + mt * 16 + g) * 132;
            const int rowB = rowA + 8 * 132;
            float sA = 0.f, sB = 0.f;
#pragma unroll
            for (int nt = 0; nt < 4; ++nt) {
                float p0 = __expf(acc[mt][nt][0]);
                float p1 = __expf(acc[mt][nt][1]);
                float p2 = __expf(acc[mt][nt][2]);
                float p3 = __expf(acc[mt][nt][3]);
                sA += p0 + p1;
                sB += p2 + p3;
                const int colu = warpN * 16 + nt * 4 + tig;
                P2[rowA + colu] = f2bf2(p0, p1);
                P2[rowB + colu] = f2bf2(p2, p3);
            }
            sA += __shfl_xor_sync(0xffffffffu, sA, 1);
            sA += __shfl_xor_sync(0xffffffffu, sA, 2);
            sB += __shfl_xor_sync(0xffffffffu, sB, 1);
            sB += __shfl_xor_sync(0xffffffffu, sB, 2);
            if (tig == 0) {
                RS[(m0 + mt * 16 + g) * 9 + warpN] = sA;
                RS[(m0 + mt * 16 + 8 + g) * 9 + warpN] = sB;
            }
        }
    }
    __syncthreads();   // P2/RS complete; K2 dead (AOP alias safe)

    // ---- Stage B: warp = 16 px x 32 ch over its 128-kv half ----
    {
        const int pxg = wid >> 1, kvh = wid & 1;
        const int m0b = pxg * 16;
        float accB[4][4];
#pragma unroll
        for (int n2 = 0; n2 < 4; ++n2)
#pragma unroll
            for (int u = 0; u < 4; ++u) accB[n2][u] = 0.f;

#pragma unroll
        for (int j = 0; j < 8; ++j) {
            const int kt = kvh * 8 + j;
            uint32_t a[4];
            a[0] = P2[(m0b + g) * 132 + kt * 8 + tig];
            a[1] = P2[(m0b + 8 + g) * 132 + kt * 8 + tig];
            a[2] = P2[(m0b + g) * 132 + kt * 8 + 4 + tig];
            a[3] = P2[(m0b + 8 + g) * 132 + kt * 8 + 4 + tig];
#pragma unroll
            for (int n2 = 0; n2 < 4; ++n2) {
                uint32_t b0 = V2[(n2 * 8 + g) * 132 + kt * 8 + tig];
                uint32_t b1 = V2[(n2 * 8 + g) * 132 + kt * 8 + 4 + tig];
                mma16816(accB[n2], a, b0, b1);
            }
        }

        // store fp32 partials to AOP[kvh][px][34]
        float* aw = AOP + kvh * (128 * 34);
#pragma unroll
        for (int n2 = 0; n2 < 4; ++n2) {
            const int ch = n2 * 8 + 2 * tig;
            aw[(m0b + g) * 34 + ch]     = accB[n2][0];
            aw[(m0b + g) * 34 + ch + 1] = accB[n2][1];
            aw[(m0b + 8 + g) * 34 + ch]     = accB[n2][2];
            aw[(m0b + 8 + g) * 34 + ch + 1] = accB[n2][3];
        }
    }
    __syncthreads();

    // ---- reduce halves, normalize, pack ao hi/lo into Q2 alias ----
    for (int item = t; item < 2048; item += 512) {
        const int pix = item & 127, kp = item >> 7;
        float inv = 0.f;
#pragma unroll
        for (int w = 0; w < 8; ++w) inv += RS[pix * 9 + w];
        inv = 1.f / inv;
        float s0 = AOP[pix * 34 + 2 * kp]     + AOP[128 * 34 + pix * 34 + 2 * kp];
        float s1 = AOP[pix * 34 + 2 * kp + 1] + AOP[128 * 34 + pix * 34 + 2 * kp + 1];
        s0 *= inv; s1 *= inv;
        uint32_t hi = f2bf2(s0, s1);
        Q2hi[pix * 20 + kp] = hi;
        Q2lo[pix * 20 + kp] = f2bf2(s0 - bf_lo(hi), s1 - bf_hi(hi));
    }
    __syncthreads();

    // ---- Stage C: warp = 16 px x 128 o  (ao hi/lo 2-pass) ----
    {
        const int wM = wid >> 1, wN = wid & 1;
        const int m0c = wM * 16;
        float acc2[16][4];
#pragma unroll
        for (int nt = 0; nt < 16; ++nt)
#pragma unroll
            for (int u = 0; u < 4; ++u) acc2[nt][u] = 0.f;

#pragma unroll
        for (int ks = 0; ks < 2; ++ks) {
            const int kk = ks * 8 + tig;
            uint32_t Ahi[4], Alo[4];
            const int r0 = (m0c + g) * 20;
            const int r8 = r0 + 8 * 20;
            Ahi[0] = Q2hi[r0 + kk];  Ahi[1] = Q2hi[r8 + kk];
            Ahi[2] = Q2hi[r0 + kk + 4]; Ahi[3] = Q2hi[r8 + kk + 4];
            Alo[0] = Q2lo[r0 + kk];  Alo[1] = Q2lo[r8 + kk];
            Alo[2] = Q2lo[r0 + kk + 4]; Alo[3] = Q2lo[r8 + kk + 4];
#pragma unroll
            for (int nt = 0; nt < 16; ++nt) {
                const int col = (wN * 128 + nt * 8 + g) * 20;
                uint32_t b0 = Wo2[col + kk], b1 = Wo2[col + kk + 4];
                mma16816(acc2[nt], Ahi, b0, b1);
                mma16816(acc2[nt], Alo, b0, b1);
            }
        }

        const float gam = __ldg(gamma);
        const int n = b >> 6, gy = (b >> 3) & 7, gx = b & 7;
        const int pg0 = pixbase + m0c + g;
        const int i0 = pg0 >> 5, j0 = pg0 & 31;
        const size_t base0 = (size_t)n * (256 * 65536)
                           + (size_t)(gy * 32 + i0) * 256 + gx * 32 + j0;

#pragma unroll
        for (int nt = 0; nt < 16; ++nt) {
            const int o = wN * 128 + nt * 8 + 2 * tig;
            const float bo0 = __ldg(bo + o);
            const float bo1 = __ldg(bo + o + 1);
            const size_t a0 = base0 + (size_t)o * 65536;
            const size_t a1 = a0 + 65536;
            out[a0]     = fmaf(gam, acc2[nt][0] + bo0, x[a0]);
            out[a1]     = fmaf(gam, acc2[nt][1] + bo1, x[a1]);
            out[a0 + 8] = fmaf(gam, acc2[nt][2] + bo0, x[a0 + 8]);
            out[a1 + 8] = fmaf(gam, acc2[nt][3] + bo1, x[a1 + 8]);
        }
    }
}

// ---------------------------------------------------------------------------
extern "C" void kernel_launch(void* const* d_in, const int* in_sizes, int n_in,
                              void* d_out, int out_size)
{
    const float* x  = (const float*)d_in[0];
    const float* Wq = (const float*)d_in[1];
    const float* bq = (const float*)d_in[2];
    const float* Wk = (const float*)d_in[3];
    const float* bk = (const float*)d_in[4];
    const float* Wv = (const float*)d_in[5];
    const float* bv = (const float*)d_in[6];
    const float* Wo = (const float*)d_in[7];
    const float* bo = (const float*)d_in[8];
    const float* gamma = (const float*)d_in[9];
    float* out = (float*)d_out;

    cudaFuncSetAttribute(qkv_mma_kernel, cudaFuncAttributeMaxDynamicSharedMemorySize, QKV_SMEM);
    cudaFuncSetAttribute(pool_pack_kernel, cudaFuncAttributeMaxDynamicSharedMemorySize, POOL_SMEM);
    cudaFuncSetAttribute(attn_mma_kernel, cudaFuncAttributeMaxDynamicSharedMemorySize, ATTN_SMEM);

    qkv_mma_kernel<<<2048, 512, QKV_SMEM>>>(x, Wq, bq, Wk, bk, Wv, bv);
    pool_pack_kernel<<<513, 256, POOL_SMEM>>>(Wo);
    attn_mma_kernel<<<4096, 512, ATTN_SMEM>>>(bo, gamma, x, out);
}